// round 8
// baseline (speedup 1.0000x reference)
#include <cuda_runtime.h>
#include <cuda_bf16.h>
#include <math.h>

#define N_NODES 18432
#define HDIM    256
#define EDIM    64
#define FDIM    512
#define NLAY    2
#define E_BIG   294912
#define E_SML   65536

// ---------------- scratch (device globals; no allocs allowed) ----------------
__device__ float g_xl [N_NODES*HDIM];
__device__ float g_xr [N_NODES*HDIM];
__device__ float g_qkv[12][N_NODES*HDIM];     // 12 projection buffers
__device__ float g_msg[2*N_NODES*512];        // msgL | msgR, row stride 512
__device__ float g_den[2*N_NODES*16];         // denL | denR, row stride 16
__device__ float g_agg[2][N_NODES*HDIM];
__device__ float g_hid[2][N_NODES*FDIM];
__device__ float g_qe [4][N_NODES*512];       // per-set q projected to edge space
__device__ float g_wea[4][N_NODES*512];       // per-set ex-weighted ea scatter

__device__ __forceinline__ float gelu_f(float x){
    return 0.5f*x*(1.0f + tanhf(0.7978845608028654f*(x + 0.044715f*x*x*x)));
}
__device__ __forceinline__ unsigned tf32_of(float x){
    unsigned r;
    asm("cvt.rna.tf32.f32 %0, %1;" : "=r"(r) : "f"(x));
    return r;
}
__device__ __forceinline__ void mma_tf32(float c[4], const unsigned a[4],
                                         unsigned b0, unsigned b1){
    asm volatile("mma.sync.aligned.m16n8k8.row.col.f32.tf32.tf32.f32 "
        "{%0,%1,%2,%3}, {%4,%5,%6,%7}, {%8,%9}, {%0,%1,%2,%3};"
        : "+f"(c[0]), "+f"(c[1]), "+f"(c[2]), "+f"(c[3])
        : "r"(a[0]), "r"(a[1]), "r"(a[2]), "r"(a[3]), "r"(b0), "r"(b1));
}

// ---------------- batched TF32 tensor-core GEMM ------------------------------
struct GP {
    const float* A[6];
    const float* B[6];
    const float* B2[6];
    const float* bias[6];
    const float* den[6];
    float*       C[6];
    int N;
};

template<int KT, bool BIAS, bool GELU, bool NORM, bool SPLITB>
__global__ __launch_bounds__(256,2) void tgemm_k(GP p)
{
    const int z = blockIdx.z;
    const float* __restrict__ A = p.A[z];
    const float* __restrict__ B = p.B[z];
    float* __restrict__ C = p.C[z];
    const int N = p.N;

    __shared__ unsigned As[2][16][136];
    __shared__ unsigned Bs[2][16][136];

    const int tid = threadIdx.x;
    const int bx = blockIdx.x, by = blockIdx.y;
    const int warp = tid >> 5, lane = tid & 31;
    const int wm = warp >> 1, wn = warp & 1;
    const int g  = lane >> 2, c = lane & 3;

    const int arow  = tid & 127;
    const int ahalf = (tid >> 7) * 8;
    const int bk    = tid >> 4;
    const int bn    = (tid & 15) * 8;
    const int grow  = by*128 + arow;
    const float* Abase = A + (size_t)grow*KT + ahalf;
    const float* Bp    = B + (size_t)bk*N + bx*128 + bn;
    const float* dptr  = NORM ? (p.den[z] + (size_t)grow*16) : nullptr;

    float acc[2][8][4];
    #pragma unroll
    for (int mi=0;mi<2;mi++)
        #pragma unroll
        for (int ni=0;ni<8;ni++)
            #pragma unroll
            for (int r=0;r<4;r++) acc[mi][ni][r]=0.f;

    float4 av0,av1,bv0,bv1;
    av0 = *(const float4*)(Abase);   av1 = *(const float4*)(Abase+4);
    bv0 = *(const float4*)(Bp);      bv1 = *(const float4*)(Bp+4);
    Bp += (size_t)16*N;
    if (NORM){
        float rd = 1.0f/(dptr[ahalf>>5] + 1e-9f);
        av0.x*=rd; av0.y*=rd; av0.z*=rd; av0.w*=rd;
        av1.x*=rd; av1.y*=rd; av1.z*=rd; av1.w*=rd;
    }
    As[0][ahalf+0][arow]=tf32_of(av0.x); As[0][ahalf+1][arow]=tf32_of(av0.y);
    As[0][ahalf+2][arow]=tf32_of(av0.z); As[0][ahalf+3][arow]=tf32_of(av0.w);
    As[0][ahalf+4][arow]=tf32_of(av1.x); As[0][ahalf+5][arow]=tf32_of(av1.y);
    As[0][ahalf+6][arow]=tf32_of(av1.z); As[0][ahalf+7][arow]=tf32_of(av1.w);
    {
        unsigned* br = &Bs[0][bk][bn];
        br[0]=tf32_of(bv0.x); br[1]=tf32_of(bv0.y); br[2]=tf32_of(bv0.z); br[3]=tf32_of(bv0.w);
        br[4]=tf32_of(bv1.x); br[5]=tf32_of(bv1.y); br[6]=tf32_of(bv1.z); br[7]=tf32_of(bv1.w);
    }
    __syncthreads();

    int buf = 0;
    #pragma unroll 4
    for (int k0=16;k0<=KT;k0+=16){
        const bool has_next = (k0 < KT);
        if (has_next){
            if (SPLITB && k0 == 256)
                Bp = p.B2[z] + (size_t)bk*N + bx*128 + bn;
            av0 = *(const float4*)(Abase + k0);   av1 = *(const float4*)(Abase + k0 + 4);
            bv0 = *(const float4*)(Bp);           bv1 = *(const float4*)(Bp + 4);
            Bp += (size_t)16*N;
            if (NORM){
                float rd = 1.0f/(dptr[(k0+ahalf)>>5] + 1e-9f);
                av0.x*=rd; av0.y*=rd; av0.z*=rd; av0.w*=rd;
                av1.x*=rd; av1.y*=rd; av1.z*=rd; av1.w*=rd;
            }
        }
        #pragma unroll
        for (int ks=0;ks<16;ks+=8){
            unsigned af[2][4];
            #pragma unroll
            for (int mi=0;mi<2;mi++){
                const int mr = wm*32 + mi*16;
                af[mi][0] = As[buf][ks+c  ][mr+g];
                af[mi][1] = As[buf][ks+c  ][mr+g+8];
                af[mi][2] = As[buf][ks+c+4][mr+g];
                af[mi][3] = As[buf][ks+c+4][mr+g+8];
            }
            #pragma unroll
            for (int ni=0;ni<8;ni++){
                const int nc = wn*64 + ni*8 + g;
                unsigned b0 = Bs[buf][ks+c  ][nc];
                unsigned b1 = Bs[buf][ks+c+4][nc];
                mma_tf32(acc[0][ni], af[0], b0, b1);
                mma_tf32(acc[1][ni], af[1], b0, b1);
            }
        }
        if (has_next){
            const int nb = buf ^ 1;
            As[nb][ahalf+0][arow]=tf32_of(av0.x); As[nb][ahalf+1][arow]=tf32_of(av0.y);
            As[nb][ahalf+2][arow]=tf32_of(av0.z); As[nb][ahalf+3][arow]=tf32_of(av0.w);
            As[nb][ahalf+4][arow]=tf32_of(av1.x); As[nb][ahalf+5][arow]=tf32_of(av1.y);
            As[nb][ahalf+6][arow]=tf32_of(av1.z); As[nb][ahalf+7][arow]=tf32_of(av1.w);
            unsigned* br = &Bs[nb][bk][bn];
            br[0]=tf32_of(bv0.x); br[1]=tf32_of(bv0.y); br[2]=tf32_of(bv0.z); br[3]=tf32_of(bv0.w);
            br[4]=tf32_of(bv1.x); br[5]=tf32_of(bv1.y); br[6]=tf32_of(bv1.z); br[7]=tf32_of(bv1.w);
            __syncthreads();
            buf = nb;
        }
    }

    const float* bias = BIAS ? p.bias[z] : nullptr;
    #pragma unroll
    for (int mi=0;mi<2;mi++){
        const int r0 = by*128 + wm*32 + mi*16 + g;
        #pragma unroll
        for (int ni=0;ni<8;ni++){
            const int col = bx*128 + wn*64 + ni*8 + 2*c;
            float2 vA = make_float2(acc[mi][ni][0], acc[mi][ni][1]);
            float2 vB = make_float2(acc[mi][ni][2], acc[mi][ni][3]);
            if (BIAS){
                float2 b2 = *(const float2*)(bias + col);
                vA.x+=b2.x; vA.y+=b2.y; vB.x+=b2.x; vB.y+=b2.y;
            }
            if (GELU){
                vA.x=gelu_f(vA.x); vA.y=gelu_f(vA.y);
                vB.x=gelu_f(vB.x); vB.y=gelu_f(vB.y);
            }
            *(float2*)(C + (size_t)r0*N + col)     = vA;
            *(float2*)(C + (size_t)(r0+8)*N + col) = vB;
        }
    }
}

// ---------------- qe precompute: qe[n, h*64+c] = sum_d We[c,h*32+d] q[n,h*32+d]
struct QP { const float* q[4]; const float* We[4]; float* qe[4]; };

__global__ void qe_k(QP p)
{
    extern __shared__ float sWe[];   // stride 260 floats per c-row: 64*260
    const int z = blockIdx.z;
    const float* __restrict__ We = p.We[z];
    for (int i=threadIdx.x; i<EDIM*HDIM; i+=blockDim.x)
        sWe[(i>>8)*260 + (i&255)] = We[i];
    __syncthreads();
    const float* __restrict__ q = p.q[z];
    float* __restrict__ qe = p.qe[z];
    const int h = threadIdx.x >> 5, lane = threadIdx.x & 31;
    const float4* w0r = (const float4*)(sWe) + (size_t)lane*65      + h*8;
    const float4* w1r = (const float4*)(sWe) + (size_t)(lane+32)*65 + h*8;
    for (int n0 = blockIdx.x*4; n0 < N_NODES; n0 += gridDim.x*4){
        float acc0[4]={0,0,0,0}, acc1[4]={0,0,0,0};
        #pragma unroll
        for (int dq=0; dq<8; dq++){
            float4 w0 = w0r[dq];
            float4 w1 = w1r[dq];
            #pragma unroll
            for (int j=0;j<4;j++){
                float4 qv = *(const float4*)(q + (size_t)(n0+j)*256 + h*32 + dq*4);
                acc0[j] += qv.x*w0.x + qv.y*w0.y + qv.z*w0.z + qv.w*w0.w;
                acc1[j] += qv.x*w1.x + qv.y*w1.y + qv.z*w1.z + qv.w*w1.w;
            }
        }
        #pragma unroll
        for (int j=0;j<4;j++){
            qe[(size_t)(n0+j)*512 + h*64 + lane]      = acc0[j];
            qe[(size_t)(n0+j)*512 + h*64 + 32 + lane] = acc1[j];
        }
    }
}

// ---------------- unscatter: msg[n, h*32+d] += sum_c wea[n,h*64+c] We[c,h*32+d]
struct UP { const float* wea[4]; const float* We[4]; float* msg[4]; };

__global__ void unsc_k(UP p)
{
    extern __shared__ float sWeT[];   // transposed, stride 68 per (h*32+d)-row
    const int z = blockIdx.z;
    const float* __restrict__ We = p.We[z];
    for (int i=threadIdx.x; i<EDIM*HDIM; i+=blockDim.x)
        sWeT[(i&255)*68 + (i>>8)] = We[i];
    __syncthreads();
    const float* __restrict__ wea = p.wea[z];
    float* __restrict__ msg = p.msg[z];
    const int h = threadIdx.x >> 5, d = threadIdx.x & 31;
    const float4* wr = (const float4*)(sWeT) + (size_t)(h*32+d)*17;
    for (int n0 = blockIdx.x*4; n0 < N_NODES; n0 += gridDim.x*4){
        float acc[4]={0,0,0,0};
        #pragma unroll
        for (int cq=0; cq<16; cq++){
            float4 wv = wr[cq];
            #pragma unroll
            for (int j=0;j<4;j++){
                float4 wa = *(const float4*)(wea + (size_t)(n0+j)*512 + h*64 + cq*4);
                acc[j] += wa.x*wv.x + wa.y*wv.y + wa.z*wv.z + wa.w*wv.w;
            }
        }
        #pragma unroll
        for (int j=0;j<4;j++){
            float* mp = msg + (size_t)(n0+j)*512 + h*32 + d;
            *mp += acc[j];
        }
    }
}

// ---------------- restructured edge attention --------------------------------
__device__ __forceinline__ void red_add4(float* p, float4 v){
    asm volatile("red.global.add.v4.f32 [%0], {%1,%2,%3,%4};"
                 :: "l"(p), "f"(v.x), "f"(v.y), "f"(v.z), "f"(v.w) : "memory");
}

struct EP {
    const int* src; const int* dst;
    const float* ea;
    const float* q; const float* k; const float* v;
    const float* qe;
    float* msg; float* wea; float* den;
    int E;
};

// lane owns channels [8*lane, 8*lane+8) (head = lane>>2) and qe/wea cols
// [16*lane, 16*lane+16). msg/wea row stride 512, den row stride 16.
__global__ void edge2_k(EP ep)
{
    const int lane = threadIdx.x & 31;
    const int wid  = blockIdx.x*(blockDim.x>>5) + (threadIdx.x>>5);
    const int nw   = gridDim.x*(blockDim.x>>5);
    const int qoff  = lane<<3;
    const int ceoff = lane<<4;
    const bool lo_half = (lane&3) < 2;
    const int cbase = (lane&3)*16;
    const int* __restrict__ src = ep.src;
    const int* __restrict__ dst = ep.dst;
    const float* __restrict__ ea = ep.ea;
    const float* __restrict__ q = ep.q;
    const float* __restrict__ kmat = ep.k;
    const float* __restrict__ vmat = ep.v;
    const float* __restrict__ qe = ep.qe;

    for (int e = wid; e < ep.E; e += nw){
        const int si = src[e], di = dst[e];
        const float a0 = ea[(size_t)e*64 + lane];
        const float a1 = ea[(size_t)e*64 + 32 + lane];
        const float4* qr  = (const float4*)(q    + (size_t)di*256 + qoff);
        const float4* kr  = (const float4*)(kmat + (size_t)si*256 + qoff);
        const float4* qer = (const float4*)(qe   + (size_t)di*512 + ceoff);
        float4 q0=qr[0], q1=qr[1], k0=kr[0], k1=kr[1];
        float qef[16];
        *(float4*)(qef+0)  = qer[0];
        *(float4*)(qef+4)  = qer[1];
        *(float4*)(qef+8)  = qer[2];
        *(float4*)(qef+12) = qer[3];

        float part = q0.x*k0.x+q0.y*k0.y+q0.z*k0.z+q0.w*k0.w
                   + q1.x*k1.x+q1.y*k1.y+q1.z*k1.z+q1.w*k1.w;
        float eav[16];
        #pragma unroll
        for (int j=0;j<16;j++){
            int cidx = cbase + j;
            float v0 = __shfl_sync(0xffffffffu, a0, cidx);
            float v1 = __shfl_sync(0xffffffffu, a1, cidx);
            float av = lo_half ? v0 : v1;
            eav[j] = av;
            part += av * qef[j];
        }
        part += __shfl_xor_sync(0xffffffffu, part, 1);
        part += __shfl_xor_sync(0xffffffffu, part, 2);
        float ex = expf(part * 0.17677669529663687f);   // DH^-0.5

        const float4* vr = (const float4*)(vmat + (size_t)si*256 + qoff);
        float4 v0=vr[0], v1=vr[1];
        float* mp = ep.msg + (size_t)di*512 + qoff;
        red_add4(mp,   make_float4(ex*v0.x, ex*v0.y, ex*v0.z, ex*v0.w));
        red_add4(mp+4, make_float4(ex*v1.x, ex*v1.y, ex*v1.z, ex*v1.w));
        float* wp = ep.wea + (size_t)di*512 + ceoff;
        red_add4(wp,    make_float4(ex*eav[0], ex*eav[1], ex*eav[2], ex*eav[3]));
        red_add4(wp+4,  make_float4(ex*eav[4], ex*eav[5], ex*eav[6], ex*eav[7]));
        red_add4(wp+8,  make_float4(ex*eav[8], ex*eav[9], ex*eav[10],ex*eav[11]));
        red_add4(wp+12, make_float4(ex*eav[12],ex*eav[13],ex*eav[14],ex*eav[15]));
        if ((lane&3)==0)
            atomicAdd(ep.den + (size_t)di*16 + (lane>>2), ex);
    }
}

// x = LN(x + a) for both sides; grid.y selects side; one warp per row
__global__ void add_ln_k(float* __restrict__ x0, const float* __restrict__ a0,
                         float* __restrict__ x1, const float* __restrict__ a1, int M){
    int row  = blockIdx.x*(blockDim.x>>5) + (threadIdx.x>>5);
    int lane = threadIdx.x & 31;
    if (row>=M) return;
    float* x = blockIdx.y ? x1 : x0;
    const float* a = blockIdx.y ? a1 : a0;
    float vals[8]; float s=0.f;
    float* xp = x + (size_t)row*HDIM;
    const float* ap = a + (size_t)row*HDIM;
    #pragma unroll
    for (int i=0;i<8;i++){ vals[i]=xp[lane+32*i]+ap[lane+32*i]; s+=vals[i]; }
    #pragma unroll
    for (int o=16;o;o>>=1) s += __shfl_xor_sync(0xffffffffu,s,o);
    float mean=s*(1.f/HDIM);
    float vsum=0.f;
    #pragma unroll
    for (int i=0;i<8;i++){ float d=vals[i]-mean; vsum+=d*d; }
    #pragma unroll
    for (int o=16;o;o>>=1) vsum += __shfl_xor_sync(0xffffffffu,vsum,o);
    float inv = rsqrtf(vsum*(1.f/HDIM)+1e-5f);
    #pragma unroll
    for (int i=0;i<8;i++) xp[lane+32*i]=(vals[i]-mean)*inv;
}

__global__ void head2_k(const float* __restrict__ g0, const float* __restrict__ g1,
                        const float* __restrict__ w2, const float* __restrict__ b2,
                        float* __restrict__ out, int rows){
    int r=blockIdx.x*blockDim.x+threadIdx.x;
    if (r>=2*rows) return;
    const float* gr = (r < rows) ? (g0 + (size_t)r*HDIM)
                                 : (g1 + (size_t)(r-rows)*HDIM);
    float acc[7];
    #pragma unroll
    for (int j=0;j<7;j++) acc[j]=b2[j];
    for (int k2=0;k2<HDIM;k2++){
        float gv=gr[k2];
        #pragma unroll
        for (int j=0;j<7;j++) acc[j]=fmaf(gv, w2[k2*7+j], acc[j]);
    }
    float* op = out + (size_t)r*7;
    #pragma unroll
    for (int j=0;j<7;j++) op[j]=acc[j];
}

// ---------------------------- host side -------------------------------------
enum {L_XL,L_XR,L_EALL,L_EARR,L_EALR,L_EARL,L_EILL,L_EIRR,L_EILR,L_EIRL,
      L_WQ,L_WK,L_WV,L_WE,L_WO,L_F1,L_FB1,L_F2,L_FB2,L_HW1,L_HB1,L_HW2,L_HB2,L_ACT};

static const int lsize[24] = {
    4718592,4718592,18874368,18874368,4194304,4194304,
    589824,589824,131072,131072,
    524288,524288,524288,131072,524288,
    524288,2048,524288,1024,65536,256,1792,7,1};

static const int ord_dict[24]={L_XL,L_XR,L_EALL,L_EARR,L_EALR,L_EARL,
    L_EILL,L_EIRR,L_EILR,L_EIRL,
    L_WQ,L_WK,L_WV,L_WE,L_WO,L_F1,L_FB1,L_F2,L_FB2,L_HW1,L_HB1,L_HW2,L_HB2,L_ACT};
static const int ord_sig[24]={L_XL,L_XR,L_EALL,L_EARR,L_EALR,L_EARL,
    L_WQ,L_WK,L_WV,L_WE,L_WO,L_F1,L_FB1,L_F2,L_FB2,L_HW1,L_HB1,L_HW2,L_HB2,
    L_EILL,L_EIRR,L_EILR,L_EIRL,L_ACT};
static const int ord_alpha[24]={L_WE,L_WK,L_WO,L_WQ,L_WV,L_ACT,L_XL,L_XR,
    L_EALL,L_EALR,L_EARL,L_EARR,L_EILL,L_EILR,L_EIRL,L_EIRR,
    L_FB1,L_FB2,L_F1,L_F2,L_HB1,L_HB2,L_HW1,L_HW2};

extern "C" void kernel_launch(void* const* d_in, const int* in_sizes, int n_in,
                              void* d_out, int out_size)
{
    // ---- resolve input ordering by size fingerprint ----
    const int* cands[3] = {ord_dict, ord_sig, ord_alpha};
    const int* ord = nullptr;
    int lim = n_in < 24 ? n_in : 24;
    for (int c=0;c<3 && !ord;c++){
        bool ok = true;
        for (int i=0;i<lim;i++)
            if (in_sizes[i] != lsize[cands[c][i]]) { ok=false; break; }
        if (ok) ord = cands[c];
    }
    if (!ord) ord = ord_dict;
    const void* p[24] = {};
    for (int i=0;i<lim;i++) p[ord[i]] = d_in[i];

    const float* xl_in = (const float*)p[L_XL];
    const float* xr_in = (const float*)p[L_XR];
    const float* ea_ll = (const float*)p[L_EALL];
    const float* ea_rr = (const float*)p[L_EARR];
    const float* ea_lr = (const float*)p[L_EALR];
    const float* ea_rl = (const float*)p[L_EARL];
    const int*   ei_ll = (const int*)  p[L_EILL];
    const int*   ei_rr = (const int*)  p[L_EIRR];
    const int*   ei_lr = (const int*)  p[L_EILR];
    const int*   ei_rl = (const int*)  p[L_EIRL];
    const float* WQ = (const float*)p[L_WQ];
    const float* WK = (const float*)p[L_WK];
    const float* WV = (const float*)p[L_WV];
    const float* WE = (const float*)p[L_WE];
    const float* WO = (const float*)p[L_WO];
    const float* F1 = (const float*)p[L_F1];
    const float* FB1= (const float*)p[L_FB1];
    const float* F2 = (const float*)p[L_F2];
    const float* FB2= (const float*)p[L_FB2];
    const float* HW1= (const float*)p[L_HW1];
    const float* HB1= (const float*)p[L_HB1];
    const float* HW2= (const float*)p[L_HW2];
    const float* HB2= (const float*)p[L_HB2];

    float *xl,*xr,*qkv,*msg,*den,*agg,*hid,*qeB,*weaB;
    cudaGetSymbolAddress((void**)&xl,  g_xl);
    cudaGetSymbolAddress((void**)&xr,  g_xr);
    cudaGetSymbolAddress((void**)&qkv, g_qkv);
    cudaGetSymbolAddress((void**)&msg, g_msg);
    cudaGetSymbolAddress((void**)&den, g_den);
    cudaGetSymbolAddress((void**)&agg, g_agg);
    cudaGetSymbolAddress((void**)&hid, g_hid);
    cudaGetSymbolAddress((void**)&qeB, g_qe);
    cudaGetSymbolAddress((void**)&weaB,g_wea);

    float* msgL = msg;                 float* msgR = msg + (size_t)N_NODES*512;
    float* denL = den;                 float* denR = den + (size_t)N_NODES*16;
    float* aggl = agg;                 float* aggr = agg + (size_t)N_NODES*HDIM;
    float* hidL = hid;                 float* hidR = hid + (size_t)N_NODES*FDIM;
    #define QB(i)  (qkv  + (size_t)(i)*N_NODES*HDIM)
    #define QE(i)  (qeB  + (size_t)(i)*N_NODES*512)
    #define WEA(i) (weaB + (size_t)(i)*N_NODES*512)

    static const int QE_SMEM = 64*260*4;     // 66560
    static const int UN_SMEM = 256*68*4;     // 69632
    cudaFuncSetAttribute(qe_k,   cudaFuncAttributeMaxDynamicSharedMemorySize, QE_SMEM);
    cudaFuncSetAttribute(unsc_k, cudaFuncAttributeMaxDynamicSharedMemorySize, UN_SMEM);

    cudaMemcpyAsync(xl, xl_in, (size_t)N_NODES*HDIM*sizeof(float), cudaMemcpyDeviceToDevice, 0);
    cudaMemcpyAsync(xr, xr_in, (size_t)N_NODES*HDIM*sizeof(float), cudaMemcpyDeviceToDevice, 0);

    const size_t wOff = (size_t)HDIM*HDIM;
    const size_t eOff = (size_t)EDIM*HDIM;
    dim3 tb(256);

    for (int l=0;l<NLAY;l++){
        #define WQT(t) (WQ + ((size_t)l*4+(t))*wOff)
        #define WKT(t) (WK + ((size_t)l*4+(t))*wOff)
        #define WVT(t) (WV + ((size_t)l*4+(t))*wOff)
        #define WET(t) (WE + ((size_t)l*4+(t))*eOff)
        #define WOT(t) (WO + ((size_t)l*4+(t))*wOff)

        // ---- all 12 q/k/v projections, 2 launches (z=6) ----
        {
            GP pa{}; pa.N = HDIM;
            const float* Bs6[6] = {WQT(0),WKT(0),WVT(0),WQT(3),WKT(2),WVT(2)};
            for (int z2=0;z2<6;z2++){ pa.A[z2]=xl; pa.B[z2]=Bs6[z2]; pa.C[z2]=QB(z2); }
            tgemm_k<256,false,false,false,false><<<dim3(2,144,6),tb>>>(pa);
        }
        {
            GP pa{}; pa.N = HDIM;
            const float* Bs6[6] = {WQT(1),WKT(1),WVT(1),WQT(2),WKT(3),WVT(3)};
            for (int z2=0;z2<6;z2++){ pa.A[z2]=xr; pa.B[z2]=Bs6[z2]; pa.C[z2]=QB(6+z2); }
            tgemm_k<256,false,false,false,false><<<dim3(2,144,6),tb>>>(pa);
        }

        cudaMemsetAsync(msg,  0, (size_t)2*N_NODES*512*sizeof(float), 0);
        cudaMemsetAsync(den,  0, (size_t)2*N_NODES*16*sizeof(float), 0);
        cudaMemsetAsync(weaB, 0, (size_t)4*N_NODES*512*sizeof(float), 0);

        // ---- qe precompute (z=4 sets: ll, rl, rr, lr) ----
        {
            QP qp{};
            qp.q[0]=QB(0); qp.We[0]=WET(0); qp.qe[0]=QE(0);
            qp.q[1]=QB(3); qp.We[1]=WET(3); qp.qe[1]=QE(1);
            qp.q[2]=QB(6); qp.We[2]=WET(1); qp.qe[2]=QE(2);
            qp.q[3]=QB(9); qp.We[3]=WET(2); qp.qe[3]=QE(3);
            qe_k<<<dim3(592,1,4),tb,QE_SMEM>>>(qp);
        }

        // ---- 4 edge-attention sets, sequential (keep gather tables L2-hot) --
        {
            EP e0 = {ei_ll, ei_ll+E_BIG, ea_ll, QB(0), QB(1),  QB(2),  QE(0),
                     msgL,     WEA(0), denL,   E_BIG};
            EP e1 = {ei_rl, ei_rl+E_SML, ea_rl, QB(3), QB(10), QB(11), QE(1),
                     msgL+256, WEA(1), denL+8, E_SML};
            EP e2 = {ei_rr, ei_rr+E_BIG, ea_rr, QB(6), QB(7),  QB(8),  QE(2),
                     msgR,     WEA(2), denR,   E_BIG};
            EP e3 = {ei_lr, ei_lr+E_SML, ea_lr, QB(9), QB(4),  QB(5),  QE(3),
                     msgR+256, WEA(3), denR+8, E_SML};
            edge2_k<<<1184,tb>>>(e0);
            edge2_k<<<1184,tb>>>(e2);
            edge2_k<<<296,tb>>>(e1);
            edge2_k<<<296,tb>>>(e3);
        }

        // ---- unscatter wea -> msg (z=4) ----
        {
            UP up{};
            up.wea[0]=WEA(0); up.We[0]=WET(0); up.msg[0]=msgL;
            up.wea[1]=WEA(1); up.We[1]=WET(3); up.msg[1]=msgL+256;
            up.wea[2]=WEA(2); up.We[2]=WET(1); up.msg[2]=msgR;
            up.wea[3]=WEA(3); up.We[3]=WET(2); up.msg[3]=msgR+256;
            unsc_k<<<dim3(592,1,4),tb,UN_SMEM>>>(up);
        }

        // ---- output projection: agg = norm(msg) @ [Wo;Wo'] (K=512), z=2 ----
        {
            GP pw{}; pw.N = HDIM;
            pw.A[0]=msgL; pw.B[0]=WOT(0); pw.B2[0]=WOT(3); pw.den[0]=denL; pw.C[0]=aggl;
            pw.A[1]=msgR; pw.B[1]=WOT(1); pw.B2[1]=WOT(2); pw.den[1]=denR; pw.C[1]=aggr;
            tgemm_k<512,false,false,true,true><<<dim3(2,144,2),tb>>>(pw);
        }

        add_ln_k<<<dim3(N_NODES/8,2),tb>>>(xl,aggl,xr,aggr,N_NODES);

        // ---- FFN (both sides batched) ----
        {
            GP pf{}; pf.N = FDIM;
            pf.A[0]=xl; pf.B[0]=F1+((size_t)l*2+0)*HDIM*FDIM; pf.bias[0]=FB1+((size_t)l*2+0)*FDIM; pf.C[0]=hidL;
            pf.A[1]=xr; pf.B[1]=F1+((size_t)l*2+1)*HDIM*FDIM; pf.bias[1]=FB1+((size_t)l*2+1)*FDIM; pf.C[1]=hidR;
            tgemm_k<256,true,true,false,false><<<dim3(4,144,2),tb>>>(pf);
        }
        {
            GP pf{}; pf.N = HDIM;
            pf.A[0]=hidL; pf.B[0]=F2+((size_t)l*2+0)*FDIM*HDIM; pf.bias[0]=FB2+((size_t)l*2+0)*HDIM; pf.C[0]=aggl;
            pf.A[1]=hidR; pf.B[1]=F2+((size_t)l*2+1)*FDIM*HDIM; pf.bias[1]=FB2+((size_t)l*2+1)*HDIM; pf.C[1]=aggr;
            tgemm_k<512,true,false,false,false><<<dim3(2,144,2),tb>>>(pf);
        }
        add_ln_k<<<dim3(N_NODES/8,2),tb>>>(xl,aggl,xr,aggr,N_NODES);

        #undef WQT
        #undef WKT
        #undef WVT
        #undef WET
        #undef WOT
    }

    // ---- heads on rows [start, N), both sides batched ----
    int rows  = out_size / 14;          // 16384
    int start = N_NODES - rows;         // 2048
    float* out = (float*)d_out;
    {
        GP ph{}; ph.N = HDIM;
        ph.A[0]=xl + (size_t)start*HDIM; ph.B[0]=HW1; ph.bias[0]=HB1; ph.C[0]=hidL;
        ph.A[1]=xr + (size_t)start*HDIM; ph.B[1]=HW1; ph.bias[1]=HB1; ph.C[1]=hidR;
        tgemm_k<256,true,true,false,false><<<dim3(2,rows/128,2),tb>>>(ph);
    }
    head2_k<<<(2*rows+255)/256,tb>>>(hidL,hidR,HW2,HB2,out,rows);
}

// round 9
// speedup vs baseline: 1.2720x; 1.2720x over previous
#include <cuda_runtime.h>
#include <cuda_bf16.h>
#include <math.h>

#define N_NODES 18432
#define HDIM    256
#define EDIM    64
#define FDIM    512
#define NLAY    2
#define E_BIG   294912
#define E_SML   65536

// ---------------- scratch (device globals; no allocs allowed) ----------------
__device__ float g_xl [N_NODES*HDIM];
__device__ float g_xr [N_NODES*HDIM];
__device__ float g_qkv[12][N_NODES*HDIM];     // 12 projection buffers
__device__ float g_msg[2*N_NODES*512];        // msgL | msgR, row stride 512
__device__ float g_den[2*N_NODES*16];         // denL | denR, row stride 16
__device__ float g_agg[2][N_NODES*HDIM];
__device__ float g_hid[2][N_NODES*FDIM];
__device__ float g_qe [4][N_NODES*512];       // per-set q projected to edge space
__device__ float g_wea[4][N_NODES*512];       // per-set ex-weighted ea accum
// CSR scratch (edge lists are launch-constant; built once per launch)
__device__ int g_deg [4][N_NODES];
__device__ int g_off [4][N_NODES+1];
__device__ int g_cur [4][N_NODES];
__device__ int g_ssrc[4][E_BIG];
__device__ int g_seid[4][E_BIG];

__device__ __forceinline__ float gelu_f(float x){
    return 0.5f*x*(1.0f + tanhf(0.7978845608028654f*(x + 0.044715f*x*x*x)));
}
__device__ __forceinline__ unsigned tf32_of(float x){
    unsigned r;
    asm("cvt.rna.tf32.f32 %0, %1;" : "=r"(r) : "f"(x));
    return r;
}
__device__ __forceinline__ void mma_tf32(float c[4], const unsigned a[4],
                                         unsigned b0, unsigned b1){
    asm volatile("mma.sync.aligned.m16n8k8.row.col.f32.tf32.tf32.f32 "
        "{%0,%1,%2,%3}, {%4,%5,%6,%7}, {%8,%9}, {%0,%1,%2,%3};"
        : "+f"(c[0]), "+f"(c[1]), "+f"(c[2]), "+f"(c[3])
        : "r"(a[0]), "r"(a[1]), "r"(a[2]), "r"(a[3]), "r"(b0), "r"(b1));
}

// ---------------- batched TF32 tensor-core GEMM ------------------------------
struct GP {
    const float* A[6];
    const float* B[6];
    const float* B2[6];
    const float* bias[6];
    const float* den[6];
    float*       C[6];
    int N;
};

template<int KT, bool BIAS, bool GELU, bool NORM, bool SPLITB>
__global__ __launch_bounds__(256,2) void tgemm_k(GP p)
{
    const int z = blockIdx.z;
    const float* __restrict__ A = p.A[z];
    const float* __restrict__ B = p.B[z];
    float* __restrict__ C = p.C[z];
    const int N = p.N;

    __shared__ unsigned As[2][16][136];
    __shared__ unsigned Bs[2][16][136];

    const int tid = threadIdx.x;
    const int bx = blockIdx.x, by = blockIdx.y;
    const int warp = tid >> 5, lane = tid & 31;
    const int wm = warp >> 1, wn = warp & 1;
    const int g  = lane >> 2, c = lane & 3;

    const int arow  = tid & 127;
    const int ahalf = (tid >> 7) * 8;
    const int bk    = tid >> 4;
    const int bn    = (tid & 15) * 8;
    const int grow  = by*128 + arow;
    const float* Abase = A + (size_t)grow*KT + ahalf;
    const float* Bp    = B + (size_t)bk*N + bx*128 + bn;
    const float* dptr  = NORM ? (p.den[z] + (size_t)grow*16) : nullptr;

    float acc[2][8][4];
    #pragma unroll
    for (int mi=0;mi<2;mi++)
        #pragma unroll
        for (int ni=0;ni<8;ni++)
            #pragma unroll
            for (int r=0;r<4;r++) acc[mi][ni][r]=0.f;

    float4 av0,av1,bv0,bv1;
    av0 = *(const float4*)(Abase);   av1 = *(const float4*)(Abase+4);
    bv0 = *(const float4*)(Bp);      bv1 = *(const float4*)(Bp+4);
    Bp += (size_t)16*N;
    if (NORM){
        float rd = 1.0f/(dptr[ahalf>>5] + 1e-9f);
        av0.x*=rd; av0.y*=rd; av0.z*=rd; av0.w*=rd;
        av1.x*=rd; av1.y*=rd; av1.z*=rd; av1.w*=rd;
    }
    As[0][ahalf+0][arow]=tf32_of(av0.x); As[0][ahalf+1][arow]=tf32_of(av0.y);
    As[0][ahalf+2][arow]=tf32_of(av0.z); As[0][ahalf+3][arow]=tf32_of(av0.w);
    As[0][ahalf+4][arow]=tf32_of(av1.x); As[0][ahalf+5][arow]=tf32_of(av1.y);
    As[0][ahalf+6][arow]=tf32_of(av1.z); As[0][ahalf+7][arow]=tf32_of(av1.w);
    {
        unsigned* br = &Bs[0][bk][bn];
        br[0]=tf32_of(bv0.x); br[1]=tf32_of(bv0.y); br[2]=tf32_of(bv0.z); br[3]=tf32_of(bv0.w);
        br[4]=tf32_of(bv1.x); br[5]=tf32_of(bv1.y); br[6]=tf32_of(bv1.z); br[7]=tf32_of(bv1.w);
    }
    __syncthreads();

    int buf = 0;
    #pragma unroll 4
    for (int k0=16;k0<=KT;k0+=16){
        const bool has_next = (k0 < KT);
        if (has_next){
            if (SPLITB && k0 == 256)
                Bp = p.B2[z] + (size_t)bk*N + bx*128 + bn;
            av0 = *(const float4*)(Abase + k0);   av1 = *(const float4*)(Abase + k0 + 4);
            bv0 = *(const float4*)(Bp);           bv1 = *(const float4*)(Bp + 4);
            Bp += (size_t)16*N;
            if (NORM){
                float rd = 1.0f/(dptr[(k0+ahalf)>>5] + 1e-9f);
                av0.x*=rd; av0.y*=rd; av0.z*=rd; av0.w*=rd;
                av1.x*=rd; av1.y*=rd; av1.z*=rd; av1.w*=rd;
            }
        }
        #pragma unroll
        for (int ks=0;ks<16;ks+=8){
            unsigned af[2][4];
            #pragma unroll
            for (int mi=0;mi<2;mi++){
                const int mr = wm*32 + mi*16;
                af[mi][0] = As[buf][ks+c  ][mr+g];
                af[mi][1] = As[buf][ks+c  ][mr+g+8];
                af[mi][2] = As[buf][ks+c+4][mr+g];
                af[mi][3] = As[buf][ks+c+4][mr+g+8];
            }
            #pragma unroll
            for (int ni=0;ni<8;ni++){
                const int nc = wn*64 + ni*8 + g;
                unsigned b0 = Bs[buf][ks+c  ][nc];
                unsigned b1 = Bs[buf][ks+c+4][nc];
                mma_tf32(acc[0][ni], af[0], b0, b1);
                mma_tf32(acc[1][ni], af[1], b0, b1);
            }
        }
        if (has_next){
            const int nb = buf ^ 1;
            As[nb][ahalf+0][arow]=tf32_of(av0.x); As[nb][ahalf+1][arow]=tf32_of(av0.y);
            As[nb][ahalf+2][arow]=tf32_of(av0.z); As[nb][ahalf+3][arow]=tf32_of(av0.w);
            As[nb][ahalf+4][arow]=tf32_of(av1.x); As[nb][ahalf+5][arow]=tf32_of(av1.y);
            As[nb][ahalf+6][arow]=tf32_of(av1.z); As[nb][ahalf+7][arow]=tf32_of(av1.w);
            unsigned* br = &Bs[nb][bk][bn];
            br[0]=tf32_of(bv0.x); br[1]=tf32_of(bv0.y); br[2]=tf32_of(bv0.z); br[3]=tf32_of(bv0.w);
            br[4]=tf32_of(bv1.x); br[5]=tf32_of(bv1.y); br[6]=tf32_of(bv1.z); br[7]=tf32_of(bv1.w);
            __syncthreads();
            buf = nb;
        }
    }

    const float* bias = BIAS ? p.bias[z] : nullptr;
    #pragma unroll
    for (int mi=0;mi<2;mi++){
        const int r0 = by*128 + wm*32 + mi*16 + g;
        #pragma unroll
        for (int ni=0;ni<8;ni++){
            const int col = bx*128 + wn*64 + ni*8 + 2*c;
            float2 vA = make_float2(acc[mi][ni][0], acc[mi][ni][1]);
            float2 vB = make_float2(acc[mi][ni][2], acc[mi][ni][3]);
            if (BIAS){
                float2 b2 = *(const float2*)(bias + col);
                vA.x+=b2.x; vA.y+=b2.y; vB.x+=b2.x; vB.y+=b2.y;
            }
            if (GELU){
                vA.x=gelu_f(vA.x); vA.y=gelu_f(vA.y);
                vB.x=gelu_f(vB.x); vB.y=gelu_f(vB.y);
            }
            *(float2*)(C + (size_t)r0*N + col)     = vA;
            *(float2*)(C + (size_t)(r0+8)*N + col) = vB;
        }
    }
}

// ---------------- CSR build (once per launch; edge lists are constant) -------
struct CP { const int* src[4]; const int* dst[4]; int E[4]; };

__global__ void hist_k(CP p){
    const int z = blockIdx.z;
    const int* __restrict__ dst = p.dst[z];
    const int E = p.E[z];
    for (int i = blockIdx.x*blockDim.x + threadIdx.x; i < E; i += gridDim.x*blockDim.x)
        atomicAdd(&g_deg[z][dst[i]], 1);
}

__global__ void scan_k(){
    const int z = blockIdx.x;
    __shared__ int part[1024];
    const int t = threadIdx.x;
    const int base0 = t*18;                    // 1024*18 = 18432
    int local[18]; int s = 0;
    #pragma unroll
    for (int i=0;i<18;i++){ local[i] = g_deg[z][base0+i]; s += local[i]; }
    part[t] = s; __syncthreads();
    for (int o=1;o<1024;o<<=1){
        int v = (t>=o)? part[t-o] : 0;
        __syncthreads();
        part[t] += v;
        __syncthreads();
    }
    int run = (t>0)? part[t-1] : 0;
    #pragma unroll
    for (int i=0;i<18;i++){
        g_off[z][base0+i] = run;
        g_cur[z][base0+i] = run;
        run += local[i];
    }
    if (t==1023) g_off[z][N_NODES] = run;
}

__global__ void fill_k(CP p){
    const int z = blockIdx.z;
    const int* __restrict__ src = p.src[z];
    const int* __restrict__ dst = p.dst[z];
    const int E = p.E[z];
    for (int i = blockIdx.x*blockDim.x + threadIdx.x; i < E; i += gridDim.x*blockDim.x){
        int d = dst[i];
        int pos = atomicAdd(&g_cur[z][d], 1);
        g_ssrc[z][pos] = src[i];
        g_seid[z][pos] = i;
    }
}

// ---------------- qe precompute: qe[n, h*64+c] = sum_d We[c,h*32+d] q[n,h*32+d]
struct QP { const float* q[4]; const float* We[4]; float* qe[4]; };

__global__ void qe_k(QP p)
{
    extern __shared__ float sWe[];   // stride 260 floats per c-row
    const int z = blockIdx.z;
    const float* __restrict__ We = p.We[z];
    for (int i=threadIdx.x; i<EDIM*HDIM; i+=blockDim.x)
        sWe[(i>>8)*260 + (i&255)] = We[i];
    __syncthreads();
    const float* __restrict__ q = p.q[z];
    float* __restrict__ qe = p.qe[z];
    const int h = threadIdx.x >> 5, lane = threadIdx.x & 31;
    const float4* w0r = (const float4*)(sWe) + (size_t)lane*65      + h*8;
    const float4* w1r = (const float4*)(sWe) + (size_t)(lane+32)*65 + h*8;
    for (int n0 = blockIdx.x*4; n0 < N_NODES; n0 += gridDim.x*4){
        float acc0[4]={0,0,0,0}, acc1[4]={0,0,0,0};
        #pragma unroll
        for (int dq=0; dq<8; dq++){
            float4 w0 = w0r[dq];
            float4 w1 = w1r[dq];
            #pragma unroll
            for (int j=0;j<4;j++){
                float4 qv = *(const float4*)(q + (size_t)(n0+j)*256 + h*32 + dq*4);
                acc0[j] += qv.x*w0.x + qv.y*w0.y + qv.z*w0.z + qv.w*w0.w;
                acc1[j] += qv.x*w1.x + qv.y*w1.y + qv.z*w1.z + qv.w*w1.w;
            }
        }
        #pragma unroll
        for (int j=0;j<4;j++){
            qe[(size_t)(n0+j)*512 + h*64 + lane]      = acc0[j];
            qe[(size_t)(n0+j)*512 + h*64 + 32 + lane] = acc1[j];
        }
    }
}

// ---------------- unscatter: msg[n, h*32+d] += sum_c wea[n,h*64+c] We[c,h*32+d]
struct UP { const float* wea[4]; const float* We[4]; float* msg[4]; };

__global__ void unsc_k(UP p)
{
    extern __shared__ float sWeT[];   // transposed, stride 68 per (h*32+d)-row
    const int z = blockIdx.z;
    const float* __restrict__ We = p.We[z];
    for (int i=threadIdx.x; i<EDIM*HDIM; i+=blockDim.x)
        sWeT[(i&255)*68 + (i>>8)] = We[i];
    __syncthreads();
    const float* __restrict__ wea = p.wea[z];
    float* __restrict__ msg = p.msg[z];
    const int h = threadIdx.x >> 5, d = threadIdx.x & 31;
    const float4* wr = (const float4*)(sWeT) + (size_t)(h*32+d)*17;
    for (int n0 = blockIdx.x*4; n0 < N_NODES; n0 += gridDim.x*4){
        float acc[4]={0,0,0,0};
        #pragma unroll
        for (int cq=0; cq<16; cq++){
            float4 wv = wr[cq];
            #pragma unroll
            for (int j=0;j<4;j++){
                float4 wa = *(const float4*)(wea + (size_t)(n0+j)*512 + h*64 + cq*4);
                acc[j] += wa.x*wv.x + wa.y*wv.y + wa.z*wv.z + wa.w*wv.w;
            }
        }
        #pragma unroll
        for (int j=0;j<4;j++){
            float* mp = msg + (size_t)(n0+j)*512 + h*32 + d;
            *mp += acc[j];
        }
    }
}

// ---------------- CSR edge attention: one warp per destination node ----------
struct EC {
    const float* ea; const float* q; const float* k; const float* v;
    const float* qe;
    const int* off; const int* ssrc; const int* seid;
    float* msg; float* wea; float* den;   // pre-offset per side/half
};

__global__ __launch_bounds__(256) void edgec_k(EC p)
{
    const int lane = threadIdx.x & 31;
    const int node = blockIdx.x*8 + (threadIdx.x>>5);
    const int qoff  = lane<<3;
    const int ceoff = lane<<4;
    const bool lo_half = (lane&3) < 2;
    const int cbase = (lane&3)*16;

    // per-node loads (dst row)
    const float4* qr = (const float4*)(p.q + (size_t)node*256 + qoff);
    const float4 q0 = qr[0], q1 = qr[1];
    float qef[16];
    {
        const float4* qer = (const float4*)(p.qe + (size_t)node*512 + ceoff);
        *(float4*)(qef+0)  = qer[0];
        *(float4*)(qef+4)  = qer[1];
        *(float4*)(qef+8)  = qer[2];
        *(float4*)(qef+12) = qer[3];
    }
    float macc[8]  = {0,0,0,0,0,0,0,0};
    float wacc[16] = {0,0,0,0,0,0,0,0,0,0,0,0,0,0,0,0};
    float dacc = 0.f;

    const int beg = p.off[node], end = p.off[node+1];
    for (int cb = beg; cb < end; cb += 32){
        int nn = end - cb; if (nn > 32) nn = 32;
        int siv = 0, eiv = 0;
        if (lane < nn){ siv = p.ssrc[cb+lane]; eiv = p.seid[cb+lane]; }
        for (int t=0; t<nn; t++){
            const int si = __shfl_sync(0xffffffffu, siv, t);
            const int e  = __shfl_sync(0xffffffffu, eiv, t);
            const float a0 = p.ea[(size_t)e*64 + lane];
            const float a1 = p.ea[(size_t)e*64 + 32 + lane];
            const float4* kr = (const float4*)(p.k + (size_t)si*256 + qoff);
            const float4 k0 = kr[0], k1 = kr[1];
            float part = q0.x*k0.x+q0.y*k0.y+q0.z*k0.z+q0.w*k0.w
                       + q1.x*k1.x+q1.y*k1.y+q1.z*k1.z+q1.w*k1.w;
            float eav[16];
            #pragma unroll
            for (int j=0;j<16;j++){
                const int cidx = cbase + j;
                const float s0 = __shfl_sync(0xffffffffu, a0, cidx);
                const float s1 = __shfl_sync(0xffffffffu, a1, cidx);
                const float av = lo_half ? s0 : s1;
                eav[j] = av;
                part += av * qef[j];
            }
            part += __shfl_xor_sync(0xffffffffu, part, 1);
            part += __shfl_xor_sync(0xffffffffu, part, 2);
            const float ex = expf(part * 0.17677669529663687f);   // DH^-0.5

            const float4* vr = (const float4*)(p.v + (size_t)si*256 + qoff);
            const float4 v0 = vr[0], v1 = vr[1];
            macc[0]+=ex*v0.x; macc[1]+=ex*v0.y; macc[2]+=ex*v0.z; macc[3]+=ex*v0.w;
            macc[4]+=ex*v1.x; macc[5]+=ex*v1.y; macc[6]+=ex*v1.z; macc[7]+=ex*v1.w;
            #pragma unroll
            for (int j=0;j<16;j++) wacc[j] += ex*eav[j];
            dacc += ex;
        }
    }

    float* mp = p.msg + (size_t)node*512 + qoff;
    *(float4*)(mp)   = make_float4(macc[0],macc[1],macc[2],macc[3]);
    *(float4*)(mp+4) = make_float4(macc[4],macc[5],macc[6],macc[7]);
    float* wp = p.wea + (size_t)node*512 + ceoff;
    *(float4*)(wp)    = make_float4(wacc[0], wacc[1], wacc[2], wacc[3]);
    *(float4*)(wp+4)  = make_float4(wacc[4], wacc[5], wacc[6], wacc[7]);
    *(float4*)(wp+8)  = make_float4(wacc[8], wacc[9], wacc[10],wacc[11]);
    *(float4*)(wp+12) = make_float4(wacc[12],wacc[13],wacc[14],wacc[15]);
    if ((lane&3)==0)
        p.den[(size_t)node*16 + (lane>>2)] = dacc;
}

// x = LN(x + a) for both sides; grid.y selects side; one warp per row
__global__ void add_ln_k(float* __restrict__ x0, const float* __restrict__ a0,
                         float* __restrict__ x1, const float* __restrict__ a1, int M){
    int row  = blockIdx.x*(blockDim.x>>5) + (threadIdx.x>>5);
    int lane = threadIdx.x & 31;
    if (row>=M) return;
    float* x = blockIdx.y ? x1 : x0;
    const float* a = blockIdx.y ? a1 : a0;
    float vals[8]; float s=0.f;
    float* xp = x + (size_t)row*HDIM;
    const float* ap = a + (size_t)row*HDIM;
    #pragma unroll
    for (int i=0;i<8;i++){ vals[i]=xp[lane+32*i]+ap[lane+32*i]; s+=vals[i]; }
    #pragma unroll
    for (int o=16;o;o>>=1) s += __shfl_xor_sync(0xffffffffu,s,o);
    float mean=s*(1.f/HDIM);
    float vsum=0.f;
    #pragma unroll
    for (int i=0;i<8;i++){ float d=vals[i]-mean; vsum+=d*d; }
    #pragma unroll
    for (int o=16;o;o>>=1) vsum += __shfl_xor_sync(0xffffffffu,vsum,o);
    float inv = rsqrtf(vsum*(1.f/HDIM)+1e-5f);
    #pragma unroll
    for (int i=0;i<8;i++) xp[lane+32*i]=(vals[i]-mean)*inv;
}

__global__ void head2_k(const float* __restrict__ g0, const float* __restrict__ g1,
                        const float* __restrict__ w2, const float* __restrict__ b2,
                        float* __restrict__ out, int rows){
    int r=blockIdx.x*blockDim.x+threadIdx.x;
    if (r>=2*rows) return;
    const float* gr = (r < rows) ? (g0 + (size_t)r*HDIM)
                                 : (g1 + (size_t)(r-rows)*HDIM);
    float acc[7];
    #pragma unroll
    for (int j=0;j<7;j++) acc[j]=b2[j];
    for (int k2=0;k2<HDIM;k2++){
        float gv=gr[k2];
        #pragma unroll
        for (int j=0;j<7;j++) acc[j]=fmaf(gv, w2[k2*7+j], acc[j]);
    }
    float* op = out + (size_t)r*7;
    #pragma unroll
    for (int j=0;j<7;j++) op[j]=acc[j];
}

// ---------------------------- host side -------------------------------------
enum {L_XL,L_XR,L_EALL,L_EARR,L_EALR,L_EARL,L_EILL,L_EIRR,L_EILR,L_EIRL,
      L_WQ,L_WK,L_WV,L_WE,L_WO,L_F1,L_FB1,L_F2,L_FB2,L_HW1,L_HB1,L_HW2,L_HB2,L_ACT};

static const int lsize[24] = {
    4718592,4718592,18874368,18874368,4194304,4194304,
    589824,589824,131072,131072,
    524288,524288,524288,131072,524288,
    524288,2048,524288,1024,65536,256,1792,7,1};

static const int ord_dict[24]={L_XL,L_XR,L_EALL,L_EARR,L_EALR,L_EARL,
    L_EILL,L_EIRR,L_EILR,L_EIRL,
    L_WQ,L_WK,L_WV,L_WE,L_WO,L_F1,L_FB1,L_F2,L_FB2,L_HW1,L_HB1,L_HW2,L_HB2,L_ACT};
static const int ord_sig[24]={L_XL,L_XR,L_EALL,L_EARR,L_EALR,L_EARL,
    L_WQ,L_WK,L_WV,L_WE,L_WO,L_F1,L_FB1,L_F2,L_FB2,L_HW1,L_HB1,L_HW2,L_HB2,
    L_EILL,L_EIRR,L_EILR,L_EIRL,L_ACT};
static const int ord_alpha[24]={L_WE,L_WK,L_WO,L_WQ,L_WV,L_ACT,L_XL,L_XR,
    L_EALL,L_EALR,L_EARL,L_EARR,L_EILL,L_EILR,L_EIRL,L_EIRR,
    L_FB1,L_FB2,L_F1,L_F2,L_HB1,L_HB2,L_HW1,L_HW2};

extern "C" void kernel_launch(void* const* d_in, const int* in_sizes, int n_in,
                              void* d_out, int out_size)
{
    // ---- resolve input ordering by size fingerprint ----
    const int* cands[3] = {ord_dict, ord_sig, ord_alpha};
    const int* ord = nullptr;
    int lim = n_in < 24 ? n_in : 24;
    for (int c=0;c<3 && !ord;c++){
        bool ok = true;
        for (int i=0;i<lim;i++)
            if (in_sizes[i] != lsize[cands[c][i]]) { ok=false; break; }
        if (ok) ord = cands[c];
    }
    if (!ord) ord = ord_dict;
    const void* p[24] = {};
    for (int i=0;i<lim;i++) p[ord[i]] = d_in[i];

    const float* xl_in = (const float*)p[L_XL];
    const float* xr_in = (const float*)p[L_XR];
    const float* ea_ll = (const float*)p[L_EALL];
    const float* ea_rr = (const float*)p[L_EARR];
    const float* ea_lr = (const float*)p[L_EALR];
    const float* ea_rl = (const float*)p[L_EARL];
    const int*   ei_ll = (const int*)  p[L_EILL];
    const int*   ei_rr = (const int*)  p[L_EIRR];
    const int*   ei_lr = (const int*)  p[L_EILR];
    const int*   ei_rl = (const int*)  p[L_EIRL];
    const float* WQ = (const float*)p[L_WQ];
    const float* WK = (const float*)p[L_WK];
    const float* WV = (const float*)p[L_WV];
    const float* WE = (const float*)p[L_WE];
    const float* WO = (const float*)p[L_WO];
    const float* F1 = (const float*)p[L_F1];
    const float* FB1= (const float*)p[L_FB1];
    const float* F2 = (const float*)p[L_F2];
    const float* FB2= (const float*)p[L_FB2];
    const float* HW1= (const float*)p[L_HW1];
    const float* HB1= (const float*)p[L_HB1];
    const float* HW2= (const float*)p[L_HW2];
    const float* HB2= (const float*)p[L_HB2];

    float *xl,*xr,*qkv,*msg,*den,*agg,*hid,*qeB,*weaB;
    int *degB, *offB, *ssrcB, *seidB;
    cudaGetSymbolAddress((void**)&xl,  g_xl);
    cudaGetSymbolAddress((void**)&xr,  g_xr);
    cudaGetSymbolAddress((void**)&qkv, g_qkv);
    cudaGetSymbolAddress((void**)&msg, g_msg);
    cudaGetSymbolAddress((void**)&den, g_den);
    cudaGetSymbolAddress((void**)&agg, g_agg);
    cudaGetSymbolAddress((void**)&hid, g_hid);
    cudaGetSymbolAddress((void**)&qeB, g_qe);
    cudaGetSymbolAddress((void**)&weaB,g_wea);
    cudaGetSymbolAddress((void**)&degB, g_deg);
    cudaGetSymbolAddress((void**)&offB, g_off);
    cudaGetSymbolAddress((void**)&ssrcB,g_ssrc);
    cudaGetSymbolAddress((void**)&seidB,g_seid);

    float* msgL = msg;                 float* msgR = msg + (size_t)N_NODES*512;
    float* denL = den;                 float* denR = den + (size_t)N_NODES*16;
    float* aggl = agg;                 float* aggr = agg + (size_t)N_NODES*HDIM;
    float* hidL = hid;                 float* hidR = hid + (size_t)N_NODES*FDIM;
    #define QB(i)  (qkv  + (size_t)(i)*N_NODES*HDIM)
    #define QE(i)  (qeB  + (size_t)(i)*N_NODES*512)
    #define WEA(i) (weaB + (size_t)(i)*N_NODES*512)
    #define OFF(i)  (offB  + (size_t)(i)*(N_NODES+1))
    #define SSRC(i) (ssrcB + (size_t)(i)*E_BIG)
    #define SEID(i) (seidB + (size_t)(i)*E_BIG)

    static const int QE_SMEM = 64*260*4;     // 66560
    static const int UN_SMEM = 256*68*4;     // 69632
    cudaFuncSetAttribute(qe_k,   cudaFuncAttributeMaxDynamicSharedMemorySize, QE_SMEM);
    cudaFuncSetAttribute(unsc_k, cudaFuncAttributeMaxDynamicSharedMemorySize, UN_SMEM);

    cudaMemcpyAsync(xl, xl_in, (size_t)N_NODES*HDIM*sizeof(float), cudaMemcpyDeviceToDevice, 0);
    cudaMemcpyAsync(xr, xr_in, (size_t)N_NODES*HDIM*sizeof(float), cudaMemcpyDeviceToDevice, 0);

    // ---- build dst-sorted CSR once (edge lists are launch-constant) ----
    {
        cudaMemsetAsync(degB, 0, (size_t)4*N_NODES*sizeof(int), 0);
        CP cp{};
        cp.src[0]=ei_ll; cp.dst[0]=ei_ll+E_BIG; cp.E[0]=E_BIG;
        cp.src[1]=ei_rl; cp.dst[1]=ei_rl+E_SML; cp.E[1]=E_SML;
        cp.src[2]=ei_rr; cp.dst[2]=ei_rr+E_BIG; cp.E[2]=E_BIG;
        cp.src[3]=ei_lr; cp.dst[3]=ei_lr+E_SML; cp.E[3]=E_SML;
        hist_k<<<dim3(288,1,4),256>>>(cp);
        scan_k<<<4,1024>>>();
        fill_k<<<dim3(288,1,4),256>>>(cp);
    }

    const size_t wOff = (size_t)HDIM*HDIM;
    const size_t eOff = (size_t)EDIM*HDIM;
    dim3 tb(256);

    for (int l=0;l<NLAY;l++){
        #define WQT(t) (WQ + ((size_t)l*4+(t))*wOff)
        #define WKT(t) (WK + ((size_t)l*4+(t))*wOff)
        #define WVT(t) (WV + ((size_t)l*4+(t))*wOff)
        #define WET(t) (WE + ((size_t)l*4+(t))*eOff)
        #define WOT(t) (WO + ((size_t)l*4+(t))*wOff)

        // ---- all 12 q/k/v projections, 2 launches (z=6) ----
        {
            GP pa{}; pa.N = HDIM;
            const float* Bs6[6] = {WQT(0),WKT(0),WVT(0),WQT(3),WKT(2),WVT(2)};
            for (int z2=0;z2<6;z2++){ pa.A[z2]=xl; pa.B[z2]=Bs6[z2]; pa.C[z2]=QB(z2); }
            tgemm_k<256,false,false,false,false><<<dim3(2,144,6),tb>>>(pa);
        }
        {
            GP pa{}; pa.N = HDIM;
            const float* Bs6[6] = {WQT(1),WKT(1),WVT(1),WQT(2),WKT(3),WVT(3)};
            for (int z2=0;z2<6;z2++){ pa.A[z2]=xr; pa.B[z2]=Bs6[z2]; pa.C[z2]=QB(6+z2); }
            tgemm_k<256,false,false,false,false><<<dim3(2,144,6),tb>>>(pa);
        }

        // ---- qe precompute (z=4 sets: ll, rl, rr, lr) ----
        {
            QP qp{};
            qp.q[0]=QB(0); qp.We[0]=WET(0); qp.qe[0]=QE(0);
            qp.q[1]=QB(3); qp.We[1]=WET(3); qp.qe[1]=QE(1);
            qp.q[2]=QB(6); qp.We[2]=WET(1); qp.qe[2]=QE(2);
            qp.q[3]=QB(9); qp.We[3]=WET(2); qp.qe[3]=QE(3);
            qe_k<<<dim3(592,1,4),tb,QE_SMEM>>>(qp);
        }

        // ---- 4 CSR edge-attention sets, sequential (gather tables L2-hot) --
        {
            EC e0 = {ea_ll, QB(0), QB(1),  QB(2),  QE(0), OFF(0), SSRC(0), SEID(0),
                     msgL,     WEA(0), denL};
            EC e1 = {ea_rl, QB(3), QB(10), QB(11), QE(1), OFF(1), SSRC(1), SEID(1),
                     msgL+256, WEA(1), denL+8};
            EC e2 = {ea_rr, QB(6), QB(7),  QB(8),  QE(2), OFF(2), SSRC(2), SEID(2),
                     msgR,     WEA(2), denR};
            EC e3 = {ea_lr, QB(9), QB(4),  QB(5),  QE(3), OFF(3), SSRC(3), SEID(3),
                     msgR+256, WEA(3), denR+8};
            edgec_k<<<N_NODES/8,tb>>>(e0);
            edgec_k<<<N_NODES/8,tb>>>(e2);
            edgec_k<<<N_NODES/8,tb>>>(e1);
            edgec_k<<<N_NODES/8,tb>>>(e3);
        }

        // ---- unscatter wea -> msg (z=4) ----
        {
            UP up{};
            up.wea[0]=WEA(0); up.We[0]=WET(0); up.msg[0]=msgL;
            up.wea[1]=WEA(1); up.We[1]=WET(3); up.msg[1]=msgL+256;
            up.wea[2]=WEA(2); up.We[2]=WET(1); up.msg[2]=msgR;
            up.wea[3]=WEA(3); up.We[3]=WET(2); up.msg[3]=msgR+256;
            unsc_k<<<dim3(592,1,4),tb,UN_SMEM>>>(up);
        }

        // ---- output projection: agg = norm(msg) @ [Wo;Wo'] (K=512), z=2 ----
        {
            GP pw{}; pw.N = HDIM;
            pw.A[0]=msgL; pw.B[0]=WOT(0); pw.B2[0]=WOT(3); pw.den[0]=denL; pw.C[0]=aggl;
            pw.A[1]=msgR; pw.B[1]=WOT(1); pw.B2[1]=WOT(2); pw.den[1]=denR; pw.C[1]=aggr;
            tgemm_k<512,false,false,true,true><<<dim3(2,144,2),tb>>>(pw);
        }

        add_ln_k<<<dim3(N_NODES/8,2),tb>>>(xl,aggl,xr,aggr,N_NODES);

        // ---- FFN (both sides batched) ----
        {
            GP pf{}; pf.N = FDIM;
            pf.A[0]=xl; pf.B[0]=F1+((size_t)l*2+0)*HDIM*FDIM; pf.bias[0]=FB1+((size_t)l*2+0)*FDIM; pf.C[0]=hidL;
            pf.A[1]=xr; pf.B[1]=F1+((size_t)l*2+1)*HDIM*FDIM; pf.bias[1]=FB1+((size_t)l*2+1)*FDIM; pf.C[1]=hidR;
            tgemm_k<256,true,true,false,false><<<dim3(4,144,2),tb>>>(pf);
        }
        {
            GP pf{}; pf.N = HDIM;
            pf.A[0]=hidL; pf.B[0]=F2+((size_t)l*2+0)*FDIM*HDIM; pf.bias[0]=FB2+((size_t)l*2+0)*HDIM; pf.C[0]=aggl;
            pf.A[1]=hidR; pf.B[1]=F2+((size_t)l*2+1)*FDIM*HDIM; pf.bias[1]=FB2+((size_t)l*2+1)*HDIM; pf.C[1]=aggr;
            tgemm_k<512,true,false,false,false><<<dim3(2,144,2),tb>>>(pf);
        }
        add_ln_k<<<dim3(N_NODES/8,2),tb>>>(xl,aggl,xr,aggr,N_NODES);

        #undef WQT
        #undef WKT
        #undef WVT
        #undef WET
        #undef WOT
    }

    // ---- heads on rows [start, N), both sides batched ----
    int rows  = out_size / 14;          // 16384
    int start = N_NODES - rows;         // 2048
    float* out = (float*)d_out;
    {
        GP ph{}; ph.N = HDIM;
        ph.A[0]=xl + (size_t)start*HDIM; ph.B[0]=HW1; ph.bias[0]=HB1; ph.C[0]=hidL;
        ph.A[1]=xr + (size_t)start*HDIM; ph.B[1]=HW1; ph.bias[1]=HB1; ph.C[1]=hidR;
        tgemm_k<256,true,true,false,false><<<dim3(2,rows/128,2),tb>>>(ph);
    }
    head2_k<<<(2*rows+255)/256,tb>>>(hidL,hidR,HW2,HB2,out,rows);
}

// round 10
// speedup vs baseline: 1.2891x; 1.0135x over previous
#include <cuda_runtime.h>
#include <cuda_bf16.h>
#include <math.h>

#define N_NODES 18432
#define HDIM    256
#define EDIM    64
#define FDIM    512
#define NLAY    2
#define E_BIG   294912
#define E_SML   65536

// ---------------- scratch (device globals; no allocs allowed) ----------------
__device__ float g_xl [N_NODES*HDIM];
__device__ float g_xr [N_NODES*HDIM];
__device__ float g_qkv[12][N_NODES*HDIM];     // 12 projection buffers
__device__ float g_msg[2*N_NODES*512];        // msgL | msgR, row stride 512
__device__ float g_den[2*N_NODES*16];         // denL | denR, row stride 16
__device__ float g_agg[2][N_NODES*HDIM];
__device__ float g_hid[2][N_NODES*FDIM];
__device__ float g_qe [4][N_NODES*512];       // per-set q projected to edge space
__device__ float g_wea[4][N_NODES*512];       // per-set ex-weighted ea accum
// CSR scratch (edge lists are launch-constant; built once per launch)
__device__ int g_deg [4][N_NODES];
__device__ int g_off [4][N_NODES+1];
__device__ int g_cur [4][N_NODES];
__device__ int g_ssrc[4][E_BIG];
__device__ int g_seid[4][E_BIG];

__device__ __forceinline__ float gelu_f(float x){
    return 0.5f*x*(1.0f + tanhf(0.7978845608028654f*(x + 0.044715f*x*x*x)));
}
__device__ __forceinline__ unsigned tf32_of(float x){
    unsigned r;
    asm("cvt.rna.tf32.f32 %0, %1;" : "=r"(r) : "f"(x));
    return r;
}
__device__ __forceinline__ void mma_tf32(float c[4], const unsigned a[4],
                                         unsigned b0, unsigned b1){
    asm volatile("mma.sync.aligned.m16n8k8.row.col.f32.tf32.tf32.f32 "
        "{%0,%1,%2,%3}, {%4,%5,%6,%7}, {%8,%9}, {%0,%1,%2,%3};"
        : "+f"(c[0]), "+f"(c[1]), "+f"(c[2]), "+f"(c[3])
        : "r"(a[0]), "r"(a[1]), "r"(a[2]), "r"(a[3]), "r"(b0), "r"(b1));
}

// ---------------- batched TF32 tensor-core GEMM ------------------------------
// Block tile 256x128, BK=16 double-buffered, 8 warps of 64x64 (4x2 warp grid).
// Dynamic smem: As [2][16][264], Bs [2][16][136] (u32/tf32), 51200 bytes.
struct GP {
    const float* A[6];
    const float* B[6];
    const float* B2[6];
    const float* bias[6];
    const float* den[6];
    float*       C[6];
    int N;
};

#define AS_TILE 4224   // 16*264
#define BS_TILE 2176   // 16*136
#define GEMM_SMEM 51200

template<int KT, bool BIAS, bool GELU, bool NORM, bool SPLITB>
__global__ __launch_bounds__(256,1) void tgemm_k(GP p)
{
    const int z = blockIdx.z;
    const float* __restrict__ A = p.A[z];
    const float* __restrict__ B = p.B[z];
    float* __restrict__ C = p.C[z];
    const int N = p.N;

    extern __shared__ unsigned smemU[];
    unsigned* AsB = smemU;               // 2 x AS_TILE
    unsigned* BsB = smemU + 2*AS_TILE;   // 2 x BS_TILE

    const int tid = threadIdx.x;
    const int bx = blockIdx.x, by = blockIdx.y;
    const int warp = tid >> 5, lane = tid & 31;
    const int wm = warp >> 1, wn = warp & 1;          // 4x2 warp grid
    const int g  = lane >> 2, c = lane & 3;

    const int arow = tid;                             // 0..255 (A row in tile)
    const int bk   = tid >> 5;                        // 0..7
    const int bn   = (tid & 31) * 4;                  // 0..124
    const int grow = by*256 + arow;
    const float* Abase = A + (size_t)grow*KT;
    const float* dptr  = NORM ? (p.den[z] + (size_t)grow*16) : nullptr;

    float acc[4][8][4];
    #pragma unroll
    for (int mi=0;mi<4;mi++)
        #pragma unroll
        for (int ni=0;ni<8;ni++)
            #pragma unroll
            for (int r=0;r<4;r++) acc[mi][ni][r]=0.f;

    // ---- load tile k0 into regs then smem ----
    float4 a4[4]; float4 b4[2];
    {
        const float* Ap = Abase;
        #pragma unroll
        for (int j=0;j<4;j++) a4[j] = *(const float4*)(Ap + j*4);
        if (NORM){
            float rd = 1.0f/(dptr[0] + 1e-9f);
            #pragma unroll
            for (int j=0;j<4;j++){ a4[j].x*=rd; a4[j].y*=rd; a4[j].z*=rd; a4[j].w*=rd; }
        }
        b4[0] = *(const float4*)(B + (size_t)bk*N + bx*128 + bn);
        b4[1] = *(const float4*)(B + (size_t)(bk+8)*N + bx*128 + bn);
    }
    {
        unsigned* As = AsB;
        #pragma unroll
        for (int j=0;j<4;j++){
            As[(j*4+0)*264 + arow] = tf32_of(a4[j].x);
            As[(j*4+1)*264 + arow] = tf32_of(a4[j].y);
            As[(j*4+2)*264 + arow] = tf32_of(a4[j].z);
            As[(j*4+3)*264 + arow] = tf32_of(a4[j].w);
        }
        unsigned* Bs = BsB;
        unsigned* b0p = Bs + (size_t)bk*136 + bn;
        b0p[0]=tf32_of(b4[0].x); b0p[1]=tf32_of(b4[0].y);
        b0p[2]=tf32_of(b4[0].z); b0p[3]=tf32_of(b4[0].w);
        unsigned* b1p = Bs + (size_t)(bk+8)*136 + bn;
        b1p[0]=tf32_of(b4[1].x); b1p[1]=tf32_of(b4[1].y);
        b1p[2]=tf32_of(b4[1].z); b1p[3]=tf32_of(b4[1].w);
    }
    __syncthreads();

    int buf = 0;
    #pragma unroll 2
    for (int k0=16;k0<=KT;k0+=16){
        const bool has_next = (k0 < KT);
        if (has_next){
            const float* Ap = Abase + k0;
            #pragma unroll
            for (int j=0;j<4;j++) a4[j] = *(const float4*)(Ap + j*4);
            if (NORM){
                float rd = 1.0f/(dptr[k0>>5] + 1e-9f);
                #pragma unroll
                for (int j=0;j<4;j++){ a4[j].x*=rd; a4[j].y*=rd; a4[j].z*=rd; a4[j].w*=rd; }
            }
            const float* Bbase = (SPLITB && k0 >= 256) ? p.B2[z] : B;
            const int koff = (SPLITB && k0 >= 256) ? (k0 - 256) : k0;
            b4[0] = *(const float4*)(Bbase + (size_t)(koff+bk)*N + bx*128 + bn);
            b4[1] = *(const float4*)(Bbase + (size_t)(koff+bk+8)*N + bx*128 + bn);
        }
        // ---- compute on current buffer ----
        {
            const unsigned* As = AsB + (size_t)buf*AS_TILE;
            const unsigned* Bs = BsB + (size_t)buf*BS_TILE;
            #pragma unroll
            for (int ks=0;ks<16;ks+=8){
                unsigned af[4][4];
                #pragma unroll
                for (int mi=0;mi<4;mi++){
                    const int mr = wm*64 + mi*16;
                    af[mi][0] = As[(ks+c  )*264 + mr+g];
                    af[mi][1] = As[(ks+c  )*264 + mr+g+8];
                    af[mi][2] = As[(ks+c+4)*264 + mr+g];
                    af[mi][3] = As[(ks+c+4)*264 + mr+g+8];
                }
                #pragma unroll
                for (int ni=0;ni<8;ni++){
                    const int nc = wn*64 + ni*8 + g;
                    unsigned b0 = Bs[(ks+c  )*136 + nc];
                    unsigned b1 = Bs[(ks+c+4)*136 + nc];
                    #pragma unroll
                    for (int mi=0;mi<4;mi++)
                        mma_tf32(acc[mi][ni], af[mi], b0, b1);
                }
            }
        }
        if (has_next){
            const int nb = buf ^ 1;
            unsigned* As = AsB + (size_t)nb*AS_TILE;
            #pragma unroll
            for (int j=0;j<4;j++){
                As[(j*4+0)*264 + arow] = tf32_of(a4[j].x);
                As[(j*4+1)*264 + arow] = tf32_of(a4[j].y);
                As[(j*4+2)*264 + arow] = tf32_of(a4[j].z);
                As[(j*4+3)*264 + arow] = tf32_of(a4[j].w);
            }
            unsigned* Bs = BsB + (size_t)nb*BS_TILE;
            unsigned* b0p = Bs + (size_t)bk*136 + bn;
            b0p[0]=tf32_of(b4[0].x); b0p[1]=tf32_of(b4[0].y);
            b0p[2]=tf32_of(b4[0].z); b0p[3]=tf32_of(b4[0].w);
            unsigned* b1p = Bs + (size_t)(bk+8)*136 + bn;
            b1p[0]=tf32_of(b4[1].x); b1p[1]=tf32_of(b4[1].y);
            b1p[2]=tf32_of(b4[1].z); b1p[3]=tf32_of(b4[1].w);
            __syncthreads();
            buf = nb;
        }
    }

    const float* bias = BIAS ? p.bias[z] : nullptr;
    #pragma unroll
    for (int mi=0;mi<4;mi++){
        const int r0 = by*256 + wm*64 + mi*16 + g;
        #pragma unroll
        for (int ni=0;ni<8;ni++){
            const int col = bx*128 + wn*64 + ni*8 + 2*c;
            float2 vA = make_float2(acc[mi][ni][0], acc[mi][ni][1]);
            float2 vB = make_float2(acc[mi][ni][2], acc[mi][ni][3]);
            if (BIAS){
                float2 b2 = *(const float2*)(bias + col);
                vA.x+=b2.x; vA.y+=b2.y; vB.x+=b2.x; vB.y+=b2.y;
            }
            if (GELU){
                vA.x=gelu_f(vA.x); vA.y=gelu_f(vA.y);
                vB.x=gelu_f(vB.x); vB.y=gelu_f(vB.y);
            }
            *(float2*)(C + (size_t)r0*N + col)     = vA;
            *(float2*)(C + (size_t)(r0+8)*N + col) = vB;
        }
    }
}

// ---------------- CSR build (once per launch; edge lists are constant) -------
struct CP { const int* src[4]; const int* dst[4]; int E[4]; };

__global__ void hist_k(CP p){
    const int z = blockIdx.z;
    const int* __restrict__ dst = p.dst[z];
    const int E = p.E[z];
    for (int i = blockIdx.x*blockDim.x + threadIdx.x; i < E; i += gridDim.x*blockDim.x)
        atomicAdd(&g_deg[z][dst[i]], 1);
}

__global__ void scan_k(){
    const int z = blockIdx.x;
    __shared__ int part[1024];
    const int t = threadIdx.x;
    const int base0 = t*18;                    // 1024*18 = 18432
    int local[18]; int s = 0;
    #pragma unroll
    for (int i=0;i<18;i++){ local[i] = g_deg[z][base0+i]; s += local[i]; }
    part[t] = s; __syncthreads();
    for (int o=1;o<1024;o<<=1){
        int v = (t>=o)? part[t-o] : 0;
        __syncthreads();
        part[t] += v;
        __syncthreads();
    }
    int run = (t>0)? part[t-1] : 0;
    #pragma unroll
    for (int i=0;i<18;i++){
        g_off[z][base0+i] = run;
        g_cur[z][base0+i] = run;
        run += local[i];
    }
    if (t==1023) g_off[z][N_NODES] = run;
}

__global__ void fill_k(CP p){
    const int z = blockIdx.z;
    const int* __restrict__ src = p.src[z];
    const int* __restrict__ dst = p.dst[z];
    const int E = p.E[z];
    for (int i = blockIdx.x*blockDim.x + threadIdx.x; i < E; i += gridDim.x*blockDim.x){
        int d = dst[i];
        int pos = atomicAdd(&g_cur[z][d], 1);
        g_ssrc[z][pos] = src[i];
        g_seid[z][pos] = i;
    }
}

// ---------------- qe precompute: qe[n, h*64+c] = sum_d We[c,h*32+d] q[n,h*32+d]
struct QP { const float* q[4]; const float* We[4]; float* qe[4]; };

__global__ void qe_k(QP p)
{
    extern __shared__ float sWe[];   // stride 260 floats per c-row
    const int z = blockIdx.z;
    const float* __restrict__ We = p.We[z];
    for (int i=threadIdx.x; i<EDIM*HDIM; i+=blockDim.x)
        sWe[(i>>8)*260 + (i&255)] = We[i];
    __syncthreads();
    const float* __restrict__ q = p.q[z];
    float* __restrict__ qe = p.qe[z];
    const int h = threadIdx.x >> 5, lane = threadIdx.x & 31;
    const float4* w0r = (const float4*)(sWe) + (size_t)lane*65      + h*8;
    const float4* w1r = (const float4*)(sWe) + (size_t)(lane+32)*65 + h*8;
    for (int n0 = blockIdx.x*4; n0 < N_NODES; n0 += gridDim.x*4){
        float acc0[4]={0,0,0,0}, acc1[4]={0,0,0,0};
        #pragma unroll
        for (int dq=0; dq<8; dq++){
            float4 w0 = w0r[dq];
            float4 w1 = w1r[dq];
            #pragma unroll
            for (int j=0;j<4;j++){
                float4 qv = *(const float4*)(q + (size_t)(n0+j)*256 + h*32 + dq*4);
                acc0[j] += qv.x*w0.x + qv.y*w0.y + qv.z*w0.z + qv.w*w0.w;
                acc1[j] += qv.x*w1.x + qv.y*w1.y + qv.z*w1.z + qv.w*w1.w;
            }
        }
        #pragma unroll
        for (int j=0;j<4;j++){
            qe[(size_t)(n0+j)*512 + h*64 + lane]      = acc0[j];
            qe[(size_t)(n0+j)*512 + h*64 + 32 + lane] = acc1[j];
        }
    }
}

// ---------------- unscatter: msg[n, h*32+d] += sum_c wea[n,h*64+c] We[c,h*32+d]
struct UP { const float* wea[4]; const float* We[4]; float* msg[4]; };

__global__ void unsc_k(UP p)
{
    extern __shared__ float sWeT[];   // transposed, stride 68 per (h*32+d)-row
    const int z = blockIdx.z;
    const float* __restrict__ We = p.We[z];
    for (int i=threadIdx.x; i<EDIM*HDIM; i+=blockDim.x)
        sWeT[(i&255)*68 + (i>>8)] = We[i];
    __syncthreads();
    const float* __restrict__ wea = p.wea[z];
    float* __restrict__ msg = p.msg[z];
    const int h = threadIdx.x >> 5, d = threadIdx.x & 31;
    const float4* wr = (const float4*)(sWeT) + (size_t)(h*32+d)*17;
    for (int n0 = blockIdx.x*4; n0 < N_NODES; n0 += gridDim.x*4){
        float acc[4]={0,0,0,0};
        #pragma unroll
        for (int cq=0; cq<16; cq++){
            float4 wv = wr[cq];
            #pragma unroll
            for (int j=0;j<4;j++){
                float4 wa = *(const float4*)(wea + (size_t)(n0+j)*512 + h*64 + cq*4);
                acc[j] += wa.x*wv.x + wa.y*wv.y + wa.z*wv.z + wa.w*wv.w;
            }
        }
        #pragma unroll
        for (int j=0;j<4;j++){
            float* mp = msg + (size_t)(n0+j)*512 + h*32 + d;
            *mp += acc[j];
        }
    }
}

// ---------------- CSR edge attention: one warp per destination node ----------
struct EC {
    const float* ea; const float* q; const float* k; const float* v;
    const float* qe;
    const int* off; const int* ssrc; const int* seid;
    float* msg; float* wea; float* den;   // pre-offset per side/half
};

__global__ __launch_bounds__(256) void edgec_k(EC p)
{
    const int lane = threadIdx.x & 31;
    const int node = blockIdx.x*8 + (threadIdx.x>>5);
    const int qoff  = lane<<3;
    const int ceoff = lane<<4;
    const bool lo_half = (lane&3) < 2;
    const int cbase = (lane&3)*16;

    // per-node loads (dst row)
    const float4* qr = (const float4*)(p.q + (size_t)node*256 + qoff);
    const float4 q0 = qr[0], q1 = qr[1];
    float qef[16];
    {
        const float4* qer = (const float4*)(p.qe + (size_t)node*512 + ceoff);
        *(float4*)(qef+0)  = qer[0];
        *(float4*)(qef+4)  = qer[1];
        *(float4*)(qef+8)  = qer[2];
        *(float4*)(qef+12) = qer[3];
    }
    float macc[8]  = {0,0,0,0,0,0,0,0};
    float wacc[16] = {0,0,0,0,0,0,0,0,0,0,0,0,0,0,0,0};
    float dacc = 0.f;

    const int beg = p.off[node], end = p.off[node+1];
    for (int cb = beg; cb < end; cb += 32){
        int nn = end - cb; if (nn > 32) nn = 32;
        int siv = 0, eiv = 0;
        if (lane < nn){ siv = p.ssrc[cb+lane]; eiv = p.seid[cb+lane]; }
        for (int t=0; t<nn; t++){
            const int si = __shfl_sync(0xffffffffu, siv, t);
            const int e  = __shfl_sync(0xffffffffu, eiv, t);
            const float a0 = p.ea[(size_t)e*64 + lane];
            const float a1 = p.ea[(size_t)e*64 + 32 + lane];
            const float4* kr = (const float4*)(p.k + (size_t)si*256 + qoff);
            const float4 k0 = kr[0], k1 = kr[1];
            float part = q0.x*k0.x+q0.y*k0.y+q0.z*k0.z+q0.w*k0.w
                       + q1.x*k1.x+q1.y*k1.y+q1.z*k1.z+q1.w*k1.w;
            float eav[16];
            #pragma unroll
            for (int j=0;j<16;j++){
                const int cidx = cbase + j;
                const float s0 = __shfl_sync(0xffffffffu, a0, cidx);
                const float s1 = __shfl_sync(0xffffffffu, a1, cidx);
                const float av = lo_half ? s0 : s1;
                eav[j] = av;
                part += av * qef[j];
            }
            part += __shfl_xor_sync(0xffffffffu, part, 1);
            part += __shfl_xor_sync(0xffffffffu, part, 2);
            const float ex = expf(part * 0.17677669529663687f);   // DH^-0.5

            const float4* vr = (const float4*)(p.v + (size_t)si*256 + qoff);
            const float4 v0 = vr[0], v1 = vr[1];
            macc[0]+=ex*v0.x; macc[1]+=ex*v0.y; macc[2]+=ex*v0.z; macc[3]+=ex*v0.w;
            macc[4]+=ex*v1.x; macc[5]+=ex*v1.y; macc[6]+=ex*v1.z; macc[7]+=ex*v1.w;
            #pragma unroll
            for (int j=0;j<16;j++) wacc[j] += ex*eav[j];
            dacc += ex;
        }
    }

    float* mp = p.msg + (size_t)node*512 + qoff;
    *(float4*)(mp)   = make_float4(macc[0],macc[1],macc[2],macc[3]);
    *(float4*)(mp+4) = make_float4(macc[4],macc[5],macc[6],macc[7]);
    float* wp = p.wea + (size_t)node*512 + ceoff;
    *(float4*)(wp)    = make_float4(wacc[0], wacc[1], wacc[2], wacc[3]);
    *(float4*)(wp+4)  = make_float4(wacc[4], wacc[5], wacc[6], wacc[7]);
    *(float4*)(wp+8)  = make_float4(wacc[8], wacc[9], wacc[10],wacc[11]);
    *(float4*)(wp+12) = make_float4(wacc[12],wacc[13],wacc[14],wacc[15]);
    if ((lane&3)==0)
        p.den[(size_t)node*16 + (lane>>2)] = dacc;
}

// x = LN(x + a) for both sides; grid.y selects side; one warp per row
__global__ void add_ln_k(float* __restrict__ x0, const float* __restrict__ a0,
                         float* __restrict__ x1, const float* __restrict__ a1, int M){
    int row  = blockIdx.x*(blockDim.x>>5) + (threadIdx.x>>5);
    int lane = threadIdx.x & 31;
    if (row>=M) return;
    float* x = blockIdx.y ? x1 : x0;
    const float* a = blockIdx.y ? a1 : a0;
    float vals[8]; float s=0.f;
    float* xp = x + (size_t)row*HDIM;
    const float* ap = a + (size_t)row*HDIM;
    #pragma unroll
    for (int i=0;i<8;i++){ vals[i]=xp[lane+32*i]+ap[lane+32*i]; s+=vals[i]; }
    #pragma unroll
    for (int o=16;o;o>>=1) s += __shfl_xor_sync(0xffffffffu,s,o);
    float mean=s*(1.f/HDIM);
    float vsum=0.f;
    #pragma unroll
    for (int i=0;i<8;i++){ float d=vals[i]-mean; vsum+=d*d; }
    #pragma unroll
    for (int o=16;o;o>>=1) vsum += __shfl_xor_sync(0xffffffffu,vsum,o);
    float inv = rsqrtf(vsum*(1.f/HDIM)+1e-5f);
    #pragma unroll
    for (int i=0;i<8;i++) xp[lane+32*i]=(vals[i]-mean)*inv;
}

__global__ void head2_k(const float* __restrict__ g0, const float* __restrict__ g1,
                        const float* __restrict__ w2, const float* __restrict__ b2,
                        float* __restrict__ out, int rows){
    int r=blockIdx.x*blockDim.x+threadIdx.x;
    if (r>=2*rows) return;
    const float* gr = (r < rows) ? (g0 + (size_t)r*HDIM)
                                 : (g1 + (size_t)(r-rows)*HDIM);
    float acc[7];
    #pragma unroll
    for (int j=0;j<7;j++) acc[j]=b2[j];
    for (int k2=0;k2<HDIM;k2++){
        float gv=gr[k2];
        #pragma unroll
        for (int j=0;j<7;j++) acc[j]=fmaf(gv, w2[k2*7+j], acc[j]);
    }
    float* op = out + (size_t)r*7;
    #pragma unroll
    for (int j=0;j<7;j++) op[j]=acc[j];
}

// ---------------------------- host side -------------------------------------
enum {L_XL,L_XR,L_EALL,L_EARR,L_EALR,L_EARL,L_EILL,L_EIRR,L_EILR,L_EIRL,
      L_WQ,L_WK,L_WV,L_WE,L_WO,L_F1,L_FB1,L_F2,L_FB2,L_HW1,L_HB1,L_HW2,L_HB2,L_ACT};

static const int lsize[24] = {
    4718592,4718592,18874368,18874368,4194304,4194304,
    589824,589824,131072,131072,
    524288,524288,524288,131072,524288,
    524288,2048,524288,1024,65536,256,1792,7,1};

static const int ord_dict[24]={L_XL,L_XR,L_EALL,L_EARR,L_EALR,L_EARL,
    L_EILL,L_EIRR,L_EILR,L_EIRL,
    L_WQ,L_WK,L_WV,L_WE,L_WO,L_F1,L_FB1,L_F2,L_FB2,L_HW1,L_HB1,L_HW2,L_HB2,L_ACT};
static const int ord_sig[24]={L_XL,L_XR,L_EALL,L_EARR,L_EALR,L_EARL,
    L_WQ,L_WK,L_WV,L_WE,L_WO,L_F1,L_FB1,L_F2,L_FB2,L_HW1,L_HB1,L_HW2,L_HB2,
    L_EILL,L_EIRR,L_EILR,L_EIRL,L_ACT};
static const int ord_alpha[24]={L_WE,L_WK,L_WO,L_WQ,L_WV,L_ACT,L_XL,L_XR,
    L_EALL,L_EALR,L_EARL,L_EARR,L_EILL,L_EILR,L_EIRL,L_EIRR,
    L_FB1,L_FB2,L_F1,L_F2,L_HB1,L_HB2,L_HW1,L_HW2};

extern "C" void kernel_launch(void* const* d_in, const int* in_sizes, int n_in,
                              void* d_out, int out_size)
{
    // ---- resolve input ordering by size fingerprint ----
    const int* cands[3] = {ord_dict, ord_sig, ord_alpha};
    const int* ord = nullptr;
    int lim = n_in < 24 ? n_in : 24;
    for (int c=0;c<3 && !ord;c++){
        bool ok = true;
        for (int i=0;i<lim;i++)
            if (in_sizes[i] != lsize[cands[c][i]]) { ok=false; break; }
        if (ok) ord = cands[c];
    }
    if (!ord) ord = ord_dict;
    const void* p[24] = {};
    for (int i=0;i<lim;i++) p[ord[i]] = d_in[i];

    const float* xl_in = (const float*)p[L_XL];
    const float* xr_in = (const float*)p[L_XR];
    const float* ea_ll = (const float*)p[L_EALL];
    const float* ea_rr = (const float*)p[L_EARR];
    const float* ea_lr = (const float*)p[L_EALR];
    const float* ea_rl = (const float*)p[L_EARL];
    const int*   ei_ll = (const int*)  p[L_EILL];
    const int*   ei_rr = (const int*)  p[L_EIRR];
    const int*   ei_lr = (const int*)  p[L_EILR];
    const int*   ei_rl = (const int*)  p[L_EIRL];
    const float* WQ = (const float*)p[L_WQ];
    const float* WK = (const float*)p[L_WK];
    const float* WV = (const float*)p[L_WV];
    const float* WE = (const float*)p[L_WE];
    const float* WO = (const float*)p[L_WO];
    const float* F1 = (const float*)p[L_F1];
    const float* FB1= (const float*)p[L_FB1];
    const float* F2 = (const float*)p[L_F2];
    const float* FB2= (const float*)p[L_FB2];
    const float* HW1= (const float*)p[L_HW1];
    const float* HB1= (const float*)p[L_HB1];
    const float* HW2= (const float*)p[L_HW2];
    const float* HB2= (const float*)p[L_HB2];

    float *xl,*xr,*qkv,*msg,*den,*agg,*hid,*qeB,*weaB;
    int *degB, *offB, *ssrcB, *seidB;
    cudaGetSymbolAddress((void**)&xl,  g_xl);
    cudaGetSymbolAddress((void**)&xr,  g_xr);
    cudaGetSymbolAddress((void**)&qkv, g_qkv);
    cudaGetSymbolAddress((void**)&msg, g_msg);
    cudaGetSymbolAddress((void**)&den, g_den);
    cudaGetSymbolAddress((void**)&agg, g_agg);
    cudaGetSymbolAddress((void**)&hid, g_hid);
    cudaGetSymbolAddress((void**)&qeB, g_qe);
    cudaGetSymbolAddress((void**)&weaB,g_wea);
    cudaGetSymbolAddress((void**)&degB, g_deg);
    cudaGetSymbolAddress((void**)&offB, g_off);
    cudaGetSymbolAddress((void**)&ssrcB,g_ssrc);
    cudaGetSymbolAddress((void**)&seidB,g_seid);

    float* msgL = msg;                 float* msgR = msg + (size_t)N_NODES*512;
    float* denL = den;                 float* denR = den + (size_t)N_NODES*16;
    float* aggl = agg;                 float* aggr = agg + (size_t)N_NODES*HDIM;
    float* hidL = hid;                 float* hidR = hid + (size_t)N_NODES*FDIM;
    #define QB(i)  (qkv  + (size_t)(i)*N_NODES*HDIM)
    #define QE(i)  (qeB  + (size_t)(i)*N_NODES*512)
    #define WEA(i) (weaB + (size_t)(i)*N_NODES*512)
    #define OFF(i)  (offB  + (size_t)(i)*(N_NODES+1))
    #define SSRC(i) (ssrcB + (size_t)(i)*E_BIG)
    #define SEID(i) (seidB + (size_t)(i)*E_BIG)

    static const int QE_SMEM = 64*260*4;     // 66560
    static const int UN_SMEM = 256*68*4;     // 69632
    cudaFuncSetAttribute(qe_k,   cudaFuncAttributeMaxDynamicSharedMemorySize, QE_SMEM);
    cudaFuncSetAttribute(unsc_k, cudaFuncAttributeMaxDynamicSharedMemorySize, UN_SMEM);
    cudaFuncSetAttribute(tgemm_k<256,false,false,false,false>,
                         cudaFuncAttributeMaxDynamicSharedMemorySize, GEMM_SMEM);
    cudaFuncSetAttribute(tgemm_k<512,false,false,true,true>,
                         cudaFuncAttributeMaxDynamicSharedMemorySize, GEMM_SMEM);
    cudaFuncSetAttribute(tgemm_k<256,true,true,false,false>,
                         cudaFuncAttributeMaxDynamicSharedMemorySize, GEMM_SMEM);
    cudaFuncSetAttribute(tgemm_k<512,true,false,false,false>,
                         cudaFuncAttributeMaxDynamicSharedMemorySize, GEMM_SMEM);

    cudaMemcpyAsync(xl, xl_in, (size_t)N_NODES*HDIM*sizeof(float), cudaMemcpyDeviceToDevice, 0);
    cudaMemcpyAsync(xr, xr_in, (size_t)N_NODES*HDIM*sizeof(float), cudaMemcpyDeviceToDevice, 0);

    // ---- build dst-sorted CSR once (edge lists are launch-constant) ----
    {
        cudaMemsetAsync(degB, 0, (size_t)4*N_NODES*sizeof(int), 0);
        CP cp{};
        cp.src[0]=ei_ll; cp.dst[0]=ei_ll+E_BIG; cp.E[0]=E_BIG;
        cp.src[1]=ei_rl; cp.dst[1]=ei_rl+E_SML; cp.E[1]=E_SML;
        cp.src[2]=ei_rr; cp.dst[2]=ei_rr+E_BIG; cp.E[2]=E_BIG;
        cp.src[3]=ei_lr; cp.dst[3]=ei_lr+E_SML; cp.E[3]=E_SML;
        hist_k<<<dim3(288,1,4),256>>>(cp);
        scan_k<<<4,1024>>>();
        fill_k<<<dim3(288,1,4),256>>>(cp);
    }

    const size_t wOff = (size_t)HDIM*HDIM;
    const size_t eOff = (size_t)EDIM*HDIM;
    dim3 tb(256);

    for (int l=0;l<NLAY;l++){
        #define WQT(t) (WQ + ((size_t)l*4+(t))*wOff)
        #define WKT(t) (WK + ((size_t)l*4+(t))*wOff)
        #define WVT(t) (WV + ((size_t)l*4+(t))*wOff)
        #define WET(t) (WE + ((size_t)l*4+(t))*eOff)
        #define WOT(t) (WO + ((size_t)l*4+(t))*wOff)

        // ---- all 12 q/k/v projections, 2 launches (z=6) ----
        {
            GP pa{}; pa.N = HDIM;
            const float* Bs6[6] = {WQT(0),WKT(0),WVT(0),WQT(3),WKT(2),WVT(2)};
            for (int z2=0;z2<6;z2++){ pa.A[z2]=xl; pa.B[z2]=Bs6[z2]; pa.C[z2]=QB(z2); }
            tgemm_k<256,false,false,false,false><<<dim3(2,72,6),tb,GEMM_SMEM>>>(pa);
        }
        {
            GP pa{}; pa.N = HDIM;
            const float* Bs6[6] = {WQT(1),WKT(1),WVT(1),WQT(2),WKT(3),WVT(3)};
            for (int z2=0;z2<6;z2++){ pa.A[z2]=xr; pa.B[z2]=Bs6[z2]; pa.C[z2]=QB(6+z2); }
            tgemm_k<256,false,false,false,false><<<dim3(2,72,6),tb,GEMM_SMEM>>>(pa);
        }

        // ---- qe precompute (z=4 sets: ll, rl, rr, lr) ----
        {
            QP qp{};
            qp.q[0]=QB(0); qp.We[0]=WET(0); qp.qe[0]=QE(0);
            qp.q[1]=QB(3); qp.We[1]=WET(3); qp.qe[1]=QE(1);
            qp.q[2]=QB(6); qp.We[2]=WET(1); qp.qe[2]=QE(2);
            qp.q[3]=QB(9); qp.We[3]=WET(2); qp.qe[3]=QE(3);
            qe_k<<<dim3(592,1,4),tb,QE_SMEM>>>(qp);
        }

        // ---- 4 CSR edge-attention sets, sequential (gather tables L2-hot) --
        {
            EC e0 = {ea_ll, QB(0), QB(1),  QB(2),  QE(0), OFF(0), SSRC(0), SEID(0),
                     msgL,     WEA(0), denL};
            EC e1 = {ea_rl, QB(3), QB(10), QB(11), QE(1), OFF(1), SSRC(1), SEID(1),
                     msgL+256, WEA(1), denL+8};
            EC e2 = {ea_rr, QB(6), QB(7),  QB(8),  QE(2), OFF(2), SSRC(2), SEID(2),
                     msgR,     WEA(2), denR};
            EC e3 = {ea_lr, QB(9), QB(4),  QB(5),  QE(3), OFF(3), SSRC(3), SEID(3),
                     msgR+256, WEA(3), denR+8};
            edgec_k<<<N_NODES/8,tb>>>(e0);
            edgec_k<<<N_NODES/8,tb>>>(e2);
            edgec_k<<<N_NODES/8,tb>>>(e1);
            edgec_k<<<N_NODES/8,tb>>>(e3);
        }

        // ---- unscatter wea -> msg (z=4) ----
        {
            UP up{};
            up.wea[0]=WEA(0); up.We[0]=WET(0); up.msg[0]=msgL;
            up.wea[1]=WEA(1); up.We[1]=WET(3); up.msg[1]=msgL+256;
            up.wea[2]=WEA(2); up.We[2]=WET(1); up.msg[2]=msgR;
            up.wea[3]=WEA(3); up.We[3]=WET(2); up.msg[3]=msgR+256;
            unsc_k<<<dim3(592,1,4),tb,UN_SMEM>>>(up);
        }

        // ---- output projection: agg = norm(msg) @ [Wo;Wo'] (K=512), z=2 ----
        {
            GP pw{}; pw.N = HDIM;
            pw.A[0]=msgL; pw.B[0]=WOT(0); pw.B2[0]=WOT(3); pw.den[0]=denL; pw.C[0]=aggl;
            pw.A[1]=msgR; pw.B[1]=WOT(1); pw.B2[1]=WOT(2); pw.den[1]=denR; pw.C[1]=aggr;
            tgemm_k<512,false,false,true,true><<<dim3(2,72,2),tb,GEMM_SMEM>>>(pw);
        }

        add_ln_k<<<dim3(N_NODES/8,2),tb>>>(xl,aggl,xr,aggr,N_NODES);

        // ---- FFN (both sides batched) ----
        {
            GP pf{}; pf.N = FDIM;
            pf.A[0]=xl; pf.B[0]=F1+((size_t)l*2+0)*HDIM*FDIM; pf.bias[0]=FB1+((size_t)l*2+0)*FDIM; pf.C[0]=hidL;
            pf.A[1]=xr; pf.B[1]=F1+((size_t)l*2+1)*HDIM*FDIM; pf.bias[1]=FB1+((size_t)l*2+1)*FDIM; pf.C[1]=hidR;
            tgemm_k<256,true,true,false,false><<<dim3(4,72,2),tb,GEMM_SMEM>>>(pf);
        }
        {
            GP pf{}; pf.N = HDIM;
            pf.A[0]=hidL; pf.B[0]=F2+((size_t)l*2+0)*FDIM*HDIM; pf.bias[0]=FB2+((size_t)l*2+0)*HDIM; pf.C[0]=aggl;
            pf.A[1]=hidR; pf.B[1]=F2+((size_t)l*2+1)*FDIM*HDIM; pf.bias[1]=FB2+((size_t)l*2+1)*HDIM; pf.C[1]=aggr;
            tgemm_k<512,true,false,false,false><<<dim3(2,72,2),tb,GEMM_SMEM>>>(pf);
        }
        add_ln_k<<<dim3(N_NODES/8,2),tb>>>(xl,aggl,xr,aggr,N_NODES);

        #undef WQT
        #undef WKT
        #undef WVT
        #undef WET
        #undef WOT
    }

    // ---- heads on rows [start, N), both sides batched ----
    int rows  = out_size / 14;          // 16384
    int start = N_NODES - rows;         // 2048
    float* out = (float*)d_out;
    {
        GP ph{}; ph.N = HDIM;
        ph.A[0]=xl + (size_t)start*HDIM; ph.B[0]=HW1; ph.bias[0]=HB1; ph.C[0]=hidL;
        ph.A[1]=xr + (size_t)start*HDIM; ph.B[1]=HW1; ph.bias[1]=HB1; ph.C[1]=hidR;
        tgemm_k<256,true,true,false,false><<<dim3(2,rows/256,2),tb,GEMM_SMEM>>>(ph);
    }
    head2_k<<<(2*rows+255)/256,tb>>>(hidL,hidR,HW2,HB2,out,rows);
}

// round 11
// speedup vs baseline: 1.3100x; 1.0162x over previous
#include <cuda_runtime.h>
#include <cuda_bf16.h>
#include <math.h>

#define N_NODES 18432
#define HDIM    256
#define EDIM    64
#define FDIM    512
#define NLAY    2
#define E_BIG   294912
#define E_SML   65536

// ---------------- scratch (device globals; no allocs allowed) ----------------
__device__ float g_xl [N_NODES*HDIM];
__device__ float g_xr [N_NODES*HDIM];
__device__ float g_qkv[12][N_NODES*HDIM];     // 12 projection buffers
__device__ float g_msg[2*N_NODES*512];        // msgL | msgR, row stride 512
__device__ float g_den[2*N_NODES*16];         // denL | denR, row stride 16
__device__ float g_agg[2][N_NODES*HDIM];
__device__ float g_hid[2][N_NODES*FDIM];
__device__ float g_qe [4][N_NODES*512];       // per-set q projected to edge space
__device__ float g_wea[4][N_NODES*512];       // per-set ex-weighted ea accum
// CSR scratch (edge lists are launch-constant; built once per launch)
__device__ int g_deg [4][N_NODES];
__device__ int g_off [4][N_NODES+1];
__device__ int g_cur [4][N_NODES];
__device__ int g_ssrc[4][E_BIG];
__device__ int g_seid[4][E_BIG];

__device__ __forceinline__ float gelu_f(float x){
    return 0.5f*x*(1.0f + tanhf(0.7978845608028654f*(x + 0.044715f*x*x*x)));
}
__device__ __forceinline__ unsigned tf32_of(float x){
    unsigned r;
    asm("cvt.rna.tf32.f32 %0, %1;" : "=r"(r) : "f"(x));
    return r;
}
__device__ __forceinline__ void mma_tf32(float c[4], const unsigned a[4],
                                         unsigned b0, unsigned b1){
    asm volatile("mma.sync.aligned.m16n8k8.row.col.f32.tf32.tf32.f32 "
        "{%0,%1,%2,%3}, {%4,%5,%6,%7}, {%8,%9}, {%0,%1,%2,%3};"
        : "+f"(c[0]), "+f"(c[1]), "+f"(c[2]), "+f"(c[3])
        : "r"(a[0]), "r"(a[1]), "r"(a[2]), "r"(a[3]), "r"(b0), "r"(b1));
}

// ---------------- batched TF32 tensor-core GEMM ------------------------------
// Block tile 256x128, BK=16 double-buffered, 8 warps of 64x64 (4x2 warp grid).
// A stored in smem in FRAGMENT ORDER: one aligned uint4 per (ks,mi,c,g) frag,
// XOR-swizzled (g^(c<<1)) for conflict-free LDS.128.
//   value A[r][k]: ks=k>>3, kk=k&7, c=kk&3, half=kk>>2,
//                  mi=r>>4, g=r&7, hi=(r>>3)&1, slot=2*half+hi
//   findex = (((ks*16+mi)*4+c)*8 + (g^(c<<1)))*4 + slot
// B stored row-major [16][136] (pad for conflict-free reads), uint4 stores.
struct GP {
    const float* A[12];
    const float* B[12];
    const float* B2[12];
    const float* bias[12];
    const float* den[12];
    float*       C[12];
    int N;
};

#define AS_TILE 4096   // floats per A-frag buffer: 2*16*4*8*4
#define BS_TILE 2176   // 16*136
#define GEMM_SMEM ((2*AS_TILE + 2*BS_TILE)*4)   // 50176 bytes

template<int KT, bool BIAS, bool GELU, bool NORM, bool SPLITB>
__global__ __launch_bounds__(256,1) void tgemm_k(GP p)
{
    const int z = blockIdx.z;
    const float* __restrict__ A = p.A[z];
    const float* __restrict__ B = p.B[z];
    float* __restrict__ C = p.C[z];
    const int N = p.N;

    extern __shared__ unsigned smemU[];
    unsigned* AsB = smemU;               // 2 x AS_TILE (fragment-packed)
    unsigned* BsB = smemU + 2*AS_TILE;   // 2 x BS_TILE

    const int tid = threadIdx.x;
    const int bx = blockIdx.x, by = blockIdx.y;
    const int warp = tid >> 5, lane = tid & 31;
    const int wm = warp >> 1, wn = warp & 1;          // 4x2 warp grid
    const int g  = lane >> 2, c = lane & 3;

    const int arow = tid;                             // 0..255 (A row in tile)
    const int bk   = tid >> 5;                        // 0..7
    const int bn   = (tid & 31) * 4;                  // 0..124
    const int grow = by*256 + arow;
    const float* Abase = A + (size_t)grow*KT;
    const float* dptr  = NORM ? (p.den[z] + (size_t)grow*16) : nullptr;

    // per-thread A-store constants
    const int smi = arow >> 4;           // 0..15
    const int sg  = arow & 7;            // 0..7
    const int shi = (arow >> 3) & 1;     // 0..1

    float acc[4][8][4];
    #pragma unroll
    for (int mi=0;mi<4;mi++)
        #pragma unroll
        for (int ni=0;ni<8;ni++)
            #pragma unroll
            for (int r=0;r<4;r++) acc[mi][ni][r]=0.f;

    float4 a4[4]; float4 b4[2];
    // ---- load tile 0 into regs ----
    {
        #pragma unroll
        for (int j=0;j<4;j++) a4[j] = *(const float4*)(Abase + j*4);
        if (NORM){
            float rd = 1.0f/(dptr[0] + 1e-9f);
            #pragma unroll
            for (int j=0;j<4;j++){ a4[j].x*=rd; a4[j].y*=rd; a4[j].z*=rd; a4[j].w*=rd; }
        }
        b4[0] = *(const float4*)(B + (size_t)bk*N + bx*128 + bn);
        b4[1] = *(const float4*)(B + (size_t)(bk+8)*N + bx*128 + bn);
    }
    // ---- stage tile 0 into smem (fragment order for A) ----
    {
        unsigned* As = AsB;
        #pragma unroll
        for (int j=0;j<4;j++){
            const int base = ((j>>1)*16 + smi)*4;     // *(32) floats later
            const int sl   = 2*(j&1) + shi;
            const float* v = (const float*)&a4[j];
            #pragma unroll
            for (int t=0;t<4;t++)
                As[(base+t)*32 + ((sg^(t<<1))<<2) + sl] = tf32_of(v[t]);
        }
        unsigned* Bs = BsB;
        uint4 bu0 = make_uint4(tf32_of(b4[0].x),tf32_of(b4[0].y),tf32_of(b4[0].z),tf32_of(b4[0].w));
        uint4 bu1 = make_uint4(tf32_of(b4[1].x),tf32_of(b4[1].y),tf32_of(b4[1].z),tf32_of(b4[1].w));
        *(uint4*)&Bs[(size_t)bk*136 + bn]     = bu0;
        *(uint4*)&Bs[(size_t)(bk+8)*136 + bn] = bu1;
    }
    __syncthreads();

    int buf = 0;
    #pragma unroll 2
    for (int k0=16;k0<=KT;k0+=16){
        const bool has_next = (k0 < KT);
        if (has_next){
            const float* Ap = Abase + k0;
            #pragma unroll
            for (int j=0;j<4;j++) a4[j] = *(const float4*)(Ap + j*4);
            if (NORM){
                float rd = 1.0f/(dptr[k0>>5] + 1e-9f);
                #pragma unroll
                for (int j=0;j<4;j++){ a4[j].x*=rd; a4[j].y*=rd; a4[j].z*=rd; a4[j].w*=rd; }
            }
            const float* Bbase = (SPLITB && k0 >= 256) ? p.B2[z] : B;
            const int koff = (SPLITB && k0 >= 256) ? (k0 - 256) : k0;
            b4[0] = *(const float4*)(Bbase + (size_t)(koff+bk)*N + bx*128 + bn);
            b4[1] = *(const float4*)(Bbase + (size_t)(koff+bk+8)*N + bx*128 + bn);
        }
        // ---- compute on current buffer ----
        {
            const unsigned* As = AsB + (size_t)buf*AS_TILE;
            const unsigned* Bs = BsB + (size_t)buf*BS_TILE;
            #pragma unroll
            for (int ks=0;ks<2;ks++){
                unsigned af[4][4];
                #pragma unroll
                for (int mi=0;mi<4;mi++){
                    const int mi_abs = wm*4 + mi;
                    const uint4 av = *(const uint4*)&As[(((ks*16+mi_abs)*4 + c)*8 + (g^(c<<1)))*4];
                    af[mi][0]=av.x; af[mi][1]=av.y; af[mi][2]=av.z; af[mi][3]=av.w;
                }
                #pragma unroll
                for (int ni=0;ni<8;ni++){
                    const int nc = wn*64 + ni*8 + g;
                    unsigned b0 = Bs[(ks*8+c  )*136 + nc];
                    unsigned b1 = Bs[(ks*8+c+4)*136 + nc];
                    #pragma unroll
                    for (int mi=0;mi<4;mi++)
                        mma_tf32(acc[mi][ni], af[mi], b0, b1);
                }
            }
        }
        if (has_next){
            const int nb = buf ^ 1;
            unsigned* As = AsB + (size_t)nb*AS_TILE;
            #pragma unroll
            for (int j=0;j<4;j++){
                const int base = ((j>>1)*16 + smi)*4;
                const int sl   = 2*(j&1) + shi;
                const float* v = (const float*)&a4[j];
                #pragma unroll
                for (int t=0;t<4;t++)
                    As[(base+t)*32 + ((sg^(t<<1))<<2) + sl] = tf32_of(v[t]);
            }
            unsigned* Bs = BsB + (size_t)nb*BS_TILE;
            uint4 bu0 = make_uint4(tf32_of(b4[0].x),tf32_of(b4[0].y),tf32_of(b4[0].z),tf32_of(b4[0].w));
            uint4 bu1 = make_uint4(tf32_of(b4[1].x),tf32_of(b4[1].y),tf32_of(b4[1].z),tf32_of(b4[1].w));
            *(uint4*)&Bs[(size_t)bk*136 + bn]     = bu0;
            *(uint4*)&Bs[(size_t)(bk+8)*136 + bn] = bu1;
            __syncthreads();
            buf = nb;
        }
    }

    const float* bias = BIAS ? p.bias[z] : nullptr;
    #pragma unroll
    for (int mi=0;mi<4;mi++){
        const int r0 = by*256 + wm*64 + mi*16 + g;
        #pragma unroll
        for (int ni=0;ni<8;ni++){
            const int col = bx*128 + wn*64 + ni*8 + 2*c;
            float2 vA = make_float2(acc[mi][ni][0], acc[mi][ni][1]);
            float2 vB = make_float2(acc[mi][ni][2], acc[mi][ni][3]);
            if (BIAS){
                float2 b2 = *(const float2*)(bias + col);
                vA.x+=b2.x; vA.y+=b2.y; vB.x+=b2.x; vB.y+=b2.y;
            }
            if (GELU){
                vA.x=gelu_f(vA.x); vA.y=gelu_f(vA.y);
                vB.x=gelu_f(vB.x); vB.y=gelu_f(vB.y);
            }
            *(float2*)(C + (size_t)r0*N + col)     = vA;
            *(float2*)(C + (size_t)(r0+8)*N + col) = vB;
        }
    }
}

// ---------------- CSR build (once per launch; edge lists are constant) -------
struct CP { const int* src[4]; const int* dst[4]; int E[4]; };

__global__ void hist_k(CP p){
    const int z = blockIdx.z;
    const int* __restrict__ dst = p.dst[z];
    const int E = p.E[z];
    for (int i = blockIdx.x*blockDim.x + threadIdx.x; i < E; i += gridDim.x*blockDim.x)
        atomicAdd(&g_deg[z][dst[i]], 1);
}

__global__ void scan_k(){
    const int z = blockIdx.x;
    __shared__ int part[1024];
    const int t = threadIdx.x;
    const int base0 = t*18;                    // 1024*18 = 18432
    int local[18]; int s = 0;
    #pragma unroll
    for (int i=0;i<18;i++){ local[i] = g_deg[z][base0+i]; s += local[i]; }
    part[t] = s; __syncthreads();
    for (int o=1;o<1024;o<<=1){
        int v = (t>=o)? part[t-o] : 0;
        __syncthreads();
        part[t] += v;
        __syncthreads();
    }
    int run = (t>0)? part[t-1] : 0;
    #pragma unroll
    for (int i=0;i<18;i++){
        g_off[z][base0+i] = run;
        g_cur[z][base0+i] = run;
        run += local[i];
    }
    if (t==1023) g_off[z][N_NODES] = run;
}

__global__ void fill_k(CP p){
    const int z = blockIdx.z;
    const int* __restrict__ src = p.src[z];
    const int* __restrict__ dst = p.dst[z];
    const int E = p.E[z];
    for (int i = blockIdx.x*blockDim.x + threadIdx.x; i < E; i += gridDim.x*blockDim.x){
        int d = dst[i];
        int pos = atomicAdd(&g_cur[z][d], 1);
        g_ssrc[z][pos] = src[i];
        g_seid[z][pos] = i;
    }
}

// ---------------- qe precompute: qe[n, h*64+c] = sum_d We[c,h*32+d] q[n,h*32+d]
struct QP { const float* q[4]; const float* We[4]; float* qe[4]; };

__global__ void qe_k(QP p)
{
    extern __shared__ float sWe[];   // stride 260 floats per c-row
    const int z = blockIdx.z;
    const float* __restrict__ We = p.We[z];
    for (int i=threadIdx.x; i<EDIM*HDIM; i+=blockDim.x)
        sWe[(i>>8)*260 + (i&255)] = We[i];
    __syncthreads();
    const float* __restrict__ q = p.q[z];
    float* __restrict__ qe = p.qe[z];
    const int h = threadIdx.x >> 5, lane = threadIdx.x & 31;
    const float4* w0r = (const float4*)(sWe) + (size_t)lane*65      + h*8;
    const float4* w1r = (const float4*)(sWe) + (size_t)(lane+32)*65 + h*8;
    for (int n0 = blockIdx.x*4; n0 < N_NODES; n0 += gridDim.x*4){
        float acc0[4]={0,0,0,0}, acc1[4]={0,0,0,0};
        #pragma unroll
        for (int dq=0; dq<8; dq++){
            float4 w0 = w0r[dq];
            float4 w1 = w1r[dq];
            #pragma unroll
            for (int j=0;j<4;j++){
                float4 qv = *(const float4*)(q + (size_t)(n0+j)*256 + h*32 + dq*4);
                acc0[j] += qv.x*w0.x + qv.y*w0.y + qv.z*w0.z + qv.w*w0.w;
                acc1[j] += qv.x*w1.x + qv.y*w1.y + qv.z*w1.z + qv.w*w1.w;
            }
        }
        #pragma unroll
        for (int j=0;j<4;j++){
            qe[(size_t)(n0+j)*512 + h*64 + lane]      = acc0[j];
            qe[(size_t)(n0+j)*512 + h*64 + 32 + lane] = acc1[j];
        }
    }
}

// ---------------- unscatter: msg[n, h*32+d] += sum_c wea[n,h*64+c] We[c,h*32+d]
struct UP { const float* wea[4]; const float* We[4]; float* msg[4]; };

__global__ void unsc_k(UP p)
{
    extern __shared__ float sWeT[];   // transposed, stride 68 per (h*32+d)-row
    const int z = blockIdx.z;
    const float* __restrict__ We = p.We[z];
    for (int i=threadIdx.x; i<EDIM*HDIM; i+=blockDim.x)
        sWeT[(i&255)*68 + (i>>8)] = We[i];
    __syncthreads();
    const float* __restrict__ wea = p.wea[z];
    float* __restrict__ msg = p.msg[z];
    const int h = threadIdx.x >> 5, d = threadIdx.x & 31;
    const float4* wr = (const float4*)(sWeT) + (size_t)(h*32+d)*17;
    for (int n0 = blockIdx.x*4; n0 < N_NODES; n0 += gridDim.x*4){
        float acc[4]={0,0,0,0};
        #pragma unroll
        for (int cq=0; cq<16; cq++){
            float4 wv = wr[cq];
            #pragma unroll
            for (int j=0;j<4;j++){
                float4 wa = *(const float4*)(wea + (size_t)(n0+j)*512 + h*64 + cq*4);
                acc[j] += wa.x*wv.x + wa.y*wv.y + wa.z*wv.z + wa.w*wv.w;
            }
        }
        #pragma unroll
        for (int j=0;j<4;j++){
            float* mp = msg + (size_t)(n0+j)*512 + h*32 + d;
            *mp += acc[j];
        }
    }
}

// ---------------- CSR edge attention: one warp per destination node ----------
struct EC {
    const float* ea; const float* q; const float* k; const float* v;
    const float* qe;
    const int* off; const int* ssrc; const int* seid;
    float* msg; float* wea; float* den;   // pre-offset per side/half
};

__global__ __launch_bounds__(256) void edgec_k(EC p)
{
    const int lane = threadIdx.x & 31;
    const int node = blockIdx.x*8 + (threadIdx.x>>5);
    const int qoff  = lane<<3;
    const int ceoff = lane<<4;
    const bool lo_half = (lane&3) < 2;
    const int cbase = (lane&3)*16;

    // per-node loads (dst row)
    const float4* qr = (const float4*)(p.q + (size_t)node*256 + qoff);
    const float4 q0 = qr[0], q1 = qr[1];
    float qef[16];
    {
        const float4* qer = (const float4*)(p.qe + (size_t)node*512 + ceoff);
        *(float4*)(qef+0)  = qer[0];
        *(float4*)(qef+4)  = qer[1];
        *(float4*)(qef+8)  = qer[2];
        *(float4*)(qef+12) = qer[3];
    }
    float macc[8]  = {0,0,0,0,0,0,0,0};
    float wacc[16] = {0,0,0,0,0,0,0,0,0,0,0,0,0,0,0,0};
    float dacc = 0.f;

    const int beg = p.off[node], end = p.off[node+1];
    for (int cb = beg; cb < end; cb += 32){
        int nn = end - cb; if (nn > 32) nn = 32;
        int siv = 0, eiv = 0;
        if (lane < nn){ siv = p.ssrc[cb+lane]; eiv = p.seid[cb+lane]; }
        for (int t=0; t<nn; t++){
            const int si = __shfl_sync(0xffffffffu, siv, t);
            const int e  = __shfl_sync(0xffffffffu, eiv, t);
            const float a0 = p.ea[(size_t)e*64 + lane];
            const float a1 = p.ea[(size_t)e*64 + 32 + lane];
            const float4* kr = (const float4*)(p.k + (size_t)si*256 + qoff);
            const float4 k0 = kr[0], k1 = kr[1];
            float part = q0.x*k0.x+q0.y*k0.y+q0.z*k0.z+q0.w*k0.w
                       + q1.x*k1.x+q1.y*k1.y+q1.z*k1.z+q1.w*k1.w;
            float eav[16];
            #pragma unroll
            for (int j=0;j<16;j++){
                const int cidx = cbase + j;
                const float s0 = __shfl_sync(0xffffffffu, a0, cidx);
                const float s1 = __shfl_sync(0xffffffffu, a1, cidx);
                const float av = lo_half ? s0 : s1;
                eav[j] = av;
                part += av * qef[j];
            }
            part += __shfl_xor_sync(0xffffffffu, part, 1);
            part += __shfl_xor_sync(0xffffffffu, part, 2);
            const float ex = expf(part * 0.17677669529663687f);   // DH^-0.5

            const float4* vr = (const float4*)(p.v + (size_t)si*256 + qoff);
            const float4 v0 = vr[0], v1 = vr[1];
            macc[0]+=ex*v0.x; macc[1]+=ex*v0.y; macc[2]+=ex*v0.z; macc[3]+=ex*v0.w;
            macc[4]+=ex*v1.x; macc[5]+=ex*v1.y; macc[6]+=ex*v1.z; macc[7]+=ex*v1.w;
            #pragma unroll
            for (int j=0;j<16;j++) wacc[j] += ex*eav[j];
            dacc += ex;
        }
    }

    float* mp = p.msg + (size_t)node*512 + qoff;
    *(float4*)(mp)   = make_float4(macc[0],macc[1],macc[2],macc[3]);
    *(float4*)(mp+4) = make_float4(macc[4],macc[5],macc[6],macc[7]);
    float* wp = p.wea + (size_t)node*512 + ceoff;
    *(float4*)(wp)    = make_float4(wacc[0], wacc[1], wacc[2], wacc[3]);
    *(float4*)(wp+4)  = make_float4(wacc[4], wacc[5], wacc[6], wacc[7]);
    *(float4*)(wp+8)  = make_float4(wacc[8], wacc[9], wacc[10],wacc[11]);
    *(float4*)(wp+12) = make_float4(wacc[12],wacc[13],wacc[14],wacc[15]);
    if ((lane&3)==0)
        p.den[(size_t)node*16 + (lane>>2)] = dacc;
}

// x = LN(x + a) for both sides; grid.y selects side; one warp per row
__global__ void add_ln_k(float* __restrict__ x0, const float* __restrict__ a0,
                         float* __restrict__ x1, const float* __restrict__ a1, int M){
    int row  = blockIdx.x*(blockDim.x>>5) + (threadIdx.x>>5);
    int lane = threadIdx.x & 31;
    if (row>=M) return;
    float* x = blockIdx.y ? x1 : x0;
    const float* a = blockIdx.y ? a1 : a0;
    float vals[8]; float s=0.f;
    float* xp = x + (size_t)row*HDIM;
    const float* ap = a + (size_t)row*HDIM;
    #pragma unroll
    for (int i=0;i<8;i++){ vals[i]=xp[lane+32*i]+ap[lane+32*i]; s+=vals[i]; }
    #pragma unroll
    for (int o=16;o;o>>=1) s += __shfl_xor_sync(0xffffffffu,s,o);
    float mean=s*(1.f/HDIM);
    float vsum=0.f;
    #pragma unroll
    for (int i=0;i<8;i++){ float d=vals[i]-mean; vsum+=d*d; }
    #pragma unroll
    for (int o=16;o;o>>=1) vsum += __shfl_xor_sync(0xffffffffu,vsum,o);
    float inv = rsqrtf(vsum*(1.f/HDIM)+1e-5f);
    #pragma unroll
    for (int i=0;i<8;i++) xp[lane+32*i]=(vals[i]-mean)*inv;
}

__global__ void head2_k(const float* __restrict__ g0, const float* __restrict__ g1,
                        const float* __restrict__ w2, const float* __restrict__ b2,
                        float* __restrict__ out, int rows){
    int r=blockIdx.x*blockDim.x+threadIdx.x;
    if (r>=2*rows) return;
    const float* gr = (r < rows) ? (g0 + (size_t)r*HDIM)
                                 : (g1 + (size_t)(r-rows)*HDIM);
    float acc[7];
    #pragma unroll
    for (int j=0;j<7;j++) acc[j]=b2[j];
    for (int k2=0;k2<HDIM;k2++){
        float gv=gr[k2];
        #pragma unroll
        for (int j=0;j<7;j++) acc[j]=fmaf(gv, w2[k2*7+j], acc[j]);
    }
    float* op = out + (size_t)r*7;
    #pragma unroll
    for (int j=0;j<7;j++) op[j]=acc[j];
}

// ---------------------------- host side -------------------------------------
enum {L_XL,L_XR,L_EALL,L_EARR,L_EALR,L_EARL,L_EILL,L_EIRR,L_EILR,L_EIRL,
      L_WQ,L_WK,L_WV,L_WE,L_WO,L_F1,L_FB1,L_F2,L_FB2,L_HW1,L_HB1,L_HW2,L_HB2,L_ACT};

static const int lsize[24] = {
    4718592,4718592,18874368,18874368,4194304,4194304,
    589824,589824,131072,131072,
    524288,524288,524288,131072,524288,
    524288,2048,524288,1024,65536,256,1792,7,1};

static const int ord_dict[24]={L_XL,L_XR,L_EALL,L_EARR,L_EALR,L_EARL,
    L_EILL,L_EIRR,L_EILR,L_EIRL,
    L_WQ,L_WK,L_WV,L_WE,L_WO,L_F1,L_FB1,L_F2,L_FB2,L_HW1,L_HB1,L_HW2,L_HB2,L_ACT};
static const int ord_sig[24]={L_XL,L_XR,L_EALL,L_EARR,L_EALR,L_EARL,
    L_WQ,L_WK,L_WV,L_WE,L_WO,L_F1,L_FB1,L_F2,L_FB2,L_HW1,L_HB1,L_HW2,L_HB2,
    L_EILL,L_EIRR,L_EILR,L_EIRL,L_ACT};
static const int ord_alpha[24]={L_WE,L_WK,L_WO,L_WQ,L_WV,L_ACT,L_XL,L_XR,
    L_EALL,L_EALR,L_EARL,L_EARR,L_EILL,L_EILR,L_EIRL,L_EIRR,
    L_FB1,L_FB2,L_F1,L_F2,L_HB1,L_HB2,L_HW1,L_HW2};

extern "C" void kernel_launch(void* const* d_in, const int* in_sizes, int n_in,
                              void* d_out, int out_size)
{
    // ---- resolve input ordering by size fingerprint ----
    const int* cands[3] = {ord_dict, ord_sig, ord_alpha};
    const int* ord = nullptr;
    int lim = n_in < 24 ? n_in : 24;
    for (int c=0;c<3 && !ord;c++){
        bool ok = true;
        for (int i=0;i<lim;i++)
            if (in_sizes[i] != lsize[cands[c][i]]) { ok=false; break; }
        if (ok) ord = cands[c];
    }
    if (!ord) ord = ord_dict;
    const void* p[24] = {};
    for (int i=0;i<lim;i++) p[ord[i]] = d_in[i];

    const float* xl_in = (const float*)p[L_XL];
    const float* xr_in = (const float*)p[L_XR];
    const float* ea_ll = (const float*)p[L_EALL];
    const float* ea_rr = (const float*)p[L_EARR];
    const float* ea_lr = (const float*)p[L_EALR];
    const float* ea_rl = (const float*)p[L_EARL];
    const int*   ei_ll = (const int*)  p[L_EILL];
    const int*   ei_rr = (const int*)  p[L_EIRR];
    const int*   ei_lr = (const int*)  p[L_EILR];
    const int*   ei_rl = (const int*)  p[L_EIRL];
    const float* WQ = (const float*)p[L_WQ];
    const float* WK = (const float*)p[L_WK];
    const float* WV = (const float*)p[L_WV];
    const float* WE = (const float*)p[L_WE];
    const float* WO = (const float*)p[L_WO];
    const float* F1 = (const float*)p[L_F1];
    const float* FB1= (const float*)p[L_FB1];
    const float* F2 = (const float*)p[L_F2];
    const float* FB2= (const float*)p[L_FB2];
    const float* HW1= (const float*)p[L_HW1];
    const float* HB1= (const float*)p[L_HB1];
    const float* HW2= (const float*)p[L_HW2];
    const float* HB2= (const float*)p[L_HB2];

    float *xl,*xr,*qkv,*msg,*den,*agg,*hid,*qeB,*weaB;
    int *degB, *offB, *ssrcB, *seidB;
    cudaGetSymbolAddress((void**)&xl,  g_xl);
    cudaGetSymbolAddress((void**)&xr,  g_xr);
    cudaGetSymbolAddress((void**)&qkv, g_qkv);
    cudaGetSymbolAddress((void**)&msg, g_msg);
    cudaGetSymbolAddress((void**)&den, g_den);
    cudaGetSymbolAddress((void**)&agg, g_agg);
    cudaGetSymbolAddress((void**)&hid, g_hid);
    cudaGetSymbolAddress((void**)&qeB, g_qe);
    cudaGetSymbolAddress((void**)&weaB,g_wea);
    cudaGetSymbolAddress((void**)&degB, g_deg);
    cudaGetSymbolAddress((void**)&offB, g_off);
    cudaGetSymbolAddress((void**)&ssrcB,g_ssrc);
    cudaGetSymbolAddress((void**)&seidB,g_seid);

    float* msgL = msg;                 float* msgR = msg + (size_t)N_NODES*512;
    float* denL = den;                 float* denR = den + (size_t)N_NODES*16;
    float* aggl = agg;                 float* aggr = agg + (size_t)N_NODES*HDIM;
    float* hidL = hid;                 float* hidR = hid + (size_t)N_NODES*FDIM;
    #define QB(i)  (qkv  + (size_t)(i)*N_NODES*HDIM)
    #define QE(i)  (qeB  + (size_t)(i)*N_NODES*512)
    #define WEA(i) (weaB + (size_t)(i)*N_NODES*512)
    #define OFF(i)  (offB  + (size_t)(i)*(N_NODES+1))
    #define SSRC(i) (ssrcB + (size_t)(i)*E_BIG)
    #define SEID(i) (seidB + (size_t)(i)*E_BIG)

    static const int QE_SMEM = 64*260*4;     // 66560
    static const int UN_SMEM = 256*68*4;     // 69632
    cudaFuncSetAttribute(qe_k,   cudaFuncAttributeMaxDynamicSharedMemorySize, QE_SMEM);
    cudaFuncSetAttribute(unsc_k, cudaFuncAttributeMaxDynamicSharedMemorySize, UN_SMEM);
    cudaFuncSetAttribute(tgemm_k<256,false,false,false,false>,
                         cudaFuncAttributeMaxDynamicSharedMemorySize, GEMM_SMEM);
    cudaFuncSetAttribute(tgemm_k<512,false,false,true,true>,
                         cudaFuncAttributeMaxDynamicSharedMemorySize, GEMM_SMEM);
    cudaFuncSetAttribute(tgemm_k<256,true,true,false,false>,
                         cudaFuncAttributeMaxDynamicSharedMemorySize, GEMM_SMEM);
    cudaFuncSetAttribute(tgemm_k<512,true,false,false,false>,
                         cudaFuncAttributeMaxDynamicSharedMemorySize, GEMM_SMEM);

    cudaMemcpyAsync(xl, xl_in, (size_t)N_NODES*HDIM*sizeof(float), cudaMemcpyDeviceToDevice, 0);
    cudaMemcpyAsync(xr, xr_in, (size_t)N_NODES*HDIM*sizeof(float), cudaMemcpyDeviceToDevice, 0);

    // ---- build dst-sorted CSR once (edge lists are launch-constant) ----
    {
        cudaMemsetAsync(degB, 0, (size_t)4*N_NODES*sizeof(int), 0);
        CP cp{};
        cp.src[0]=ei_ll; cp.dst[0]=ei_ll+E_BIG; cp.E[0]=E_BIG;
        cp.src[1]=ei_rl; cp.dst[1]=ei_rl+E_SML; cp.E[1]=E_SML;
        cp.src[2]=ei_rr; cp.dst[2]=ei_rr+E_BIG; cp.E[2]=E_BIG;
        cp.src[3]=ei_lr; cp.dst[3]=ei_lr+E_SML; cp.E[3]=E_SML;
        hist_k<<<dim3(288,1,4),256>>>(cp);
        scan_k<<<4,1024>>>();
        fill_k<<<dim3(288,1,4),256>>>(cp);
    }

    const size_t wOff = (size_t)HDIM*HDIM;
    const size_t eOff = (size_t)EDIM*HDIM;
    dim3 tb(256);

    for (int l=0;l<NLAY;l++){
        #define WQT(t) (WQ + ((size_t)l*4+(t))*wOff)
        #define WKT(t) (WK + ((size_t)l*4+(t))*wOff)
        #define WVT(t) (WV + ((size_t)l*4+(t))*wOff)
        #define WET(t) (WE + ((size_t)l*4+(t))*eOff)
        #define WOT(t) (WO + ((size_t)l*4+(t))*wOff)

        // ---- all 12 q/k/v projections, ONE launch (z=12) ----
        {
            GP pa{}; pa.N = HDIM;
            const float* Bs12[12] = {WQT(0),WKT(0),WVT(0),WQT(3),WKT(2),WVT(2),
                                     WQT(1),WKT(1),WVT(1),WQT(2),WKT(3),WVT(3)};
            for (int z2=0;z2<12;z2++){
                pa.A[z2] = (z2<6) ? xl : xr;
                pa.B[z2] = Bs12[z2];
                pa.C[z2] = QB(z2);
            }
            tgemm_k<256,false,false,false,false><<<dim3(2,72,12),tb,GEMM_SMEM>>>(pa);
        }

        // ---- qe precompute (z=4 sets: ll, rl, rr, lr) ----
        {
            QP qp{};
            qp.q[0]=QB(0); qp.We[0]=WET(0); qp.qe[0]=QE(0);
            qp.q[1]=QB(3); qp.We[1]=WET(3); qp.qe[1]=QE(1);
            qp.q[2]=QB(6); qp.We[2]=WET(1); qp.qe[2]=QE(2);
            qp.q[3]=QB(9); qp.We[3]=WET(2); qp.qe[3]=QE(3);
            qe_k<<<dim3(592,1,4),tb,QE_SMEM>>>(qp);
        }

        // ---- 4 CSR edge-attention sets, sequential (gather tables L2-hot) --
        {
            EC e0 = {ea_ll, QB(0), QB(1),  QB(2),  QE(0), OFF(0), SSRC(0), SEID(0),
                     msgL,     WEA(0), denL};
            EC e1 = {ea_rl, QB(3), QB(10), QB(11), QE(1), OFF(1), SSRC(1), SEID(1),
                     msgL+256, WEA(1), denL+8};
            EC e2 = {ea_rr, QB(6), QB(7),  QB(8),  QE(2), OFF(2), SSRC(2), SEID(2),
                     msgR,     WEA(2), denR};
            EC e3 = {ea_lr, QB(9), QB(4),  QB(5),  QE(3), OFF(3), SSRC(3), SEID(3),
                     msgR+256, WEA(3), denR+8};
            edgec_k<<<N_NODES/8,tb>>>(e0);
            edgec_k<<<N_NODES/8,tb>>>(e2);
            edgec_k<<<N_NODES/8,tb>>>(e1);
            edgec_k<<<N_NODES/8,tb>>>(e3);
        }

        // ---- unscatter wea -> msg (z=4) ----
        {
            UP up{};
            up.wea[0]=WEA(0); up.We[0]=WET(0); up.msg[0]=msgL;
            up.wea[1]=WEA(1); up.We[1]=WET(3); up.msg[1]=msgL+256;
            up.wea[2]=WEA(2); up.We[2]=WET(1); up.msg[2]=msgR;
            up.wea[3]=WEA(3); up.We[3]=WET(2); up.msg[3]=msgR+256;
            unsc_k<<<dim3(592,1,4),tb,UN_SMEM>>>(up);
        }

        // ---- output projection: agg = norm(msg) @ [Wo;Wo'] (K=512), z=2 ----
        {
            GP pw{}; pw.N = HDIM;
            pw.A[0]=msgL; pw.B[0]=WOT(0); pw.B2[0]=WOT(3); pw.den[0]=denL; pw.C[0]=aggl;
            pw.A[1]=msgR; pw.B[1]=WOT(1); pw.B2[1]=WOT(2); pw.den[1]=denR; pw.C[1]=aggr;
            tgemm_k<512,false,false,true,true><<<dim3(2,72,2),tb,GEMM_SMEM>>>(pw);
        }

        add_ln_k<<<dim3(N_NODES/8,2),tb>>>(xl,aggl,xr,aggr,N_NODES);

        // ---- FFN (both sides batched) ----
        {
            GP pf{}; pf.N = FDIM;
            pf.A[0]=xl; pf.B[0]=F1+((size_t)l*2+0)*HDIM*FDIM; pf.bias[0]=FB1+((size_t)l*2+0)*FDIM; pf.C[0]=hidL;
            pf.A[1]=xr; pf.B[1]=F1+((size_t)l*2+1)*HDIM*FDIM; pf.bias[1]=FB1+((size_t)l*2+1)*FDIM; pf.C[1]=hidR;
            tgemm_k<256,true,true,false,false><<<dim3(4,72,2),tb,GEMM_SMEM>>>(pf);
        }
        {
            GP pf{}; pf.N = HDIM;
            pf.A[0]=hidL; pf.B[0]=F2+((size_t)l*2+0)*FDIM*HDIM; pf.bias[0]=FB2+((size_t)l*2+0)*HDIM; pf.C[0]=aggl;
            pf.A[1]=hidR; pf.B[1]=F2+((size_t)l*2+1)*FDIM*HDIM; pf.bias[1]=FB2+((size_t)l*2+1)*HDIM; pf.C[1]=aggr;
            tgemm_k<512,true,false,false,false><<<dim3(2,72,2),tb,GEMM_SMEM>>>(pf);
        }
        add_ln_k<<<dim3(N_NODES/8,2),tb>>>(xl,aggl,xr,aggr,N_NODES);

        #undef WQT
        #undef WKT
        #undef WVT
        #undef WET
        #undef WOT
    }

    // ---- heads on rows [start, N), both sides batched ----
    int rows  = out_size / 14;          // 16384
    int start = N_NODES - rows;         // 2048
    float* out = (float*)d_out;
    {
        GP ph{}; ph.N = HDIM;
        ph.A[0]=xl + (size_t)start*HDIM; ph.B[0]=HW1; ph.bias[0]=HB1; ph.C[0]=hidL;
        ph.A[1]=xr + (size_t)start*HDIM; ph.B[1]=HW1; ph.bias[1]=HB1; ph.C[1]=hidR;
        tgemm_k<256,true,true,false,false><<<dim3(2,rows/256,2),tb,GEMM_SMEM>>>(ph);
    }
    head2_k<<<(2*rows+255)/256,tb>>>(hidL,hidR,HW2,HB2,out,rows);
}